// round 1
// baseline (speedup 1.0000x reference)
#include <cuda_runtime.h>
#include <cuda_bf16.h>
#include <math.h>
#include <stdint.h>

// Problem constants
#define BATCH 2
#define SEQ 2048
#define DMODEL 1024
#define NHEADS 16
#define HDIM 64
#define TOPK 64
#define NROWS (BATCH * SEQ)          // 4096
#define BH (BATCH * NHEADS)          // 32

// ---------------- scratch (device globals; allocation-free rule) -------------
__device__ float g_Q[(size_t)BH * SEQ * HDIM];   // [bh, s, d] 16MB
__device__ float g_K[(size_t)BH * SEQ * HDIM];   // 16MB
__device__ float g_V[(size_t)BH * SEQ * HDIM];   // 16MB
__device__ float g_P[(size_t)BH * SEQ * SEQ];    // scores -> probs, 512MB
__device__ float g_O[(size_t)NROWS * DMODEL];    // attn output pre-Wo, 16MB

// ---------------- K1/K5: 128x128x8 SGEMM -------------------------------------
// mode 0/1/2: out = h_ssm @ W + b written into g_Q/g_K/g_V in [b,h,s,d] layout
// mode 3:     out = g_O @ Wo + bo, scaled by gate[row], written to d_out
__global__ void gemm_kernel(const float* __restrict__ A,
                            const float* __restrict__ W,
                            const float* __restrict__ bias,
                            float* __restrict__ outp,
                            const float* __restrict__ gate,
                            int mode)
{
    __shared__ float As[8][128];
    __shared__ float Bs[8][128];

    const int K = DMODEL;
    const int NC = DMODEL;
    int tid = threadIdx.x;
    int tx = tid & 15;         // 0..15
    int ty = tid >> 4;         // 0..15
    int rowTile = blockIdx.y * 128;
    int colTile = blockIdx.x * 128;

    const float* Ap = (mode == 3) ? g_O : A;
    float* Op = (mode == 0) ? g_Q : (mode == 1) ? g_K : (mode == 2) ? g_V : outp;

    int ar = tid >> 1;               // 0..127
    int ac = (tid & 1) * 4;          // 0 or 4
    int br = tid >> 5;               // 0..7
    int bc = (tid & 31) * 4;         // 0..124

    float acc[8][8];
#pragma unroll
    for (int i = 0; i < 8; i++)
#pragma unroll
        for (int j = 0; j < 8; j++) acc[i][j] = 0.0f;

    for (int k0 = 0; k0 < K; k0 += 8) {
        float4 av = *(const float4*)&Ap[(size_t)(rowTile + ar) * K + k0 + ac];
        As[ac + 0][ar] = av.x;
        As[ac + 1][ar] = av.y;
        As[ac + 2][ar] = av.z;
        As[ac + 3][ar] = av.w;
        float4 bv = *(const float4*)&W[(size_t)(k0 + br) * NC + colTile + bc];
        *(float4*)&Bs[br][bc] = bv;
        __syncthreads();
#pragma unroll
        for (int kk = 0; kk < 8; kk++) {
            float a[8], b[8];
#pragma unroll
            for (int i = 0; i < 8; i++) a[i] = As[kk][ty * 8 + i];
#pragma unroll
            for (int j = 0; j < 8; j++) b[j] = Bs[kk][tx * 8 + j];
#pragma unroll
            for (int i = 0; i < 8; i++)
#pragma unroll
                for (int j = 0; j < 8; j++) acc[i][j] = fmaf(a[i], b[j], acc[i][j]);
        }
        __syncthreads();
    }

#pragma unroll
    for (int i = 0; i < 8; i++) {
        int m = rowTile + ty * 8 + i;
#pragma unroll
        for (int j = 0; j < 8; j++) {
            int n = colTile + tx * 8 + j;
            float v = acc[i][j] + bias[n];
            if (mode < 3) {
                int b = m / SEQ;
                int s = m - b * SEQ;
                int h = n >> 6;
                int d = n & 63;
                Op[((size_t)(b * NHEADS + h) * SEQ + s) * HDIM + d] = v;
            } else {
                Op[(size_t)m * DMODEL + n] = v * gate[m];
            }
        }
    }
}

// ---------------- K2: scores = Q K^T / 8, causal, 64x64 tiles ---------------
__global__ void scores_kernel()
{
    int kt = blockIdx.x;
    int qt = blockIdx.y;
    int bh = blockIdx.z;
    if (kt > qt) return;

    __shared__ float Qs[64][65];  // [d][row]
    __shared__ float Ks[64][65];  // [d][col]

    int tid = threadIdx.x;
    const float* Qg = &g_Q[((size_t)bh * SEQ + qt * 64) * HDIM];
    const float* Kg = &g_K[((size_t)bh * SEQ + kt * 64) * HDIM];

    // load + transpose: 64x64 floats each, 4 float4 per thread
#pragma unroll
    for (int t = 0; t < 4; t++) {
        int v = tid + t * 256;
        int r = v >> 4;
        int d4 = (v & 15) * 4;
        float4 qv = *(const float4*)&Qg[(size_t)r * HDIM + d4];
        Qs[d4 + 0][r] = qv.x; Qs[d4 + 1][r] = qv.y;
        Qs[d4 + 2][r] = qv.z; Qs[d4 + 3][r] = qv.w;
        float4 kv = *(const float4*)&Kg[(size_t)r * HDIM + d4];
        Ks[d4 + 0][r] = kv.x; Ks[d4 + 1][r] = kv.y;
        Ks[d4 + 2][r] = kv.z; Ks[d4 + 3][r] = kv.w;
    }
    __syncthreads();

    int tx = tid & 15;
    int ty = tid >> 4;
    float acc[4][4];
#pragma unroll
    for (int i = 0; i < 4; i++)
#pragma unroll
        for (int j = 0; j < 4; j++) acc[i][j] = 0.0f;

#pragma unroll 8
    for (int dd = 0; dd < 64; dd++) {
        float a[4], b[4];
#pragma unroll
        for (int i = 0; i < 4; i++) a[i] = Qs[dd][ty * 4 + i];
#pragma unroll
        for (int j = 0; j < 4; j++) b[j] = Ks[dd][tx * 4 + j];
#pragma unroll
        for (int i = 0; i < 4; i++)
#pragma unroll
            for (int j = 0; j < 4; j++) acc[i][j] = fmaf(a[i], b[j], acc[i][j]);
    }

    const float scale = 0.125f;  // 1/sqrt(64)
#pragma unroll
    for (int i = 0; i < 4; i++) {
        int q = qt * 64 + ty * 4 + i;
        int kbase = kt * 64 + tx * 4;
        float4 o;
        float vv[4];
#pragma unroll
        for (int j = 0; j < 4; j++) {
            float s = acc[i][j] * scale;
            vv[j] = (kbase + j > q) ? -INFINITY : s;
        }
        o.x = vv[0]; o.y = vv[1]; o.z = vv[2]; o.w = vv[3];
        *(float4*)&g_P[((size_t)bh * SEQ + q) * SEQ + kbase] = o;
    }
}

// ---------------- K3: exact top-64 threshold + masked softmax ----------------
__global__ void topk_softmax_kernel()
{
    int row = blockIdx.x;             // 0 .. BH*SEQ-1
    int bh = row >> 11;               // /SEQ
    int q = row & (SEQ - 1);
    size_t base = ((size_t)bh * SEQ + q) * SEQ;
    int L = q + 1;
    int tid = threadIdx.x;

    __shared__ float sc[SEQ];
    __shared__ unsigned bins[256];
    __shared__ unsigned s_prefix;
    __shared__ int s_kk;
    __shared__ float red[8];
    __shared__ float s_bval;

    for (int i = tid; i < L; i += 256) sc[i] = g_P[base + i];
    if (tid == 0) s_kk = TOPK;
    __syncthreads();

    float thresh = -INFINITY;
    if (L > TOPK) {
        unsigned prefix = 0, himask = 0;
        for (int p = 24; p >= 0; p -= 8) {
            bins[tid] = 0;
            __syncthreads();
            for (int i = tid; i < L; i += 256) {
                unsigned u = __float_as_uint(sc[i]);
                unsigned key = (u & 0x80000000u) ? ~u : (u | 0x80000000u);
                if ((key & himask) == prefix)
                    atomicAdd(&bins[(key >> p) & 0xFFu], 1u);
            }
            __syncthreads();
            if (tid == 0) {
                int kk = s_kk, cum = 0, sel = 0;
                for (int b = 255; b >= 0; b--) {
                    int nb = (int)bins[b];
                    if (cum + nb >= kk) { sel = b; s_kk = kk - cum; break; }
                    cum += nb;
                }
                s_prefix = prefix | ((unsigned)sel << p);
            }
            __syncthreads();
            prefix = s_prefix;
            himask |= (0xFFu << p);
            __syncthreads();
        }
        unsigned key = prefix;
        unsigned u = (key & 0x80000000u) ? (key & 0x7FFFFFFFu) : ~key;
        thresh = __uint_as_float(u);
    }

    // row max (max element is always kept)
    float m = -INFINITY;
    for (int i = tid; i < L; i += 256) m = fmaxf(m, sc[i]);
#pragma unroll
    for (int off = 16; off; off >>= 1) m = fmaxf(m, __shfl_xor_sync(0xFFFFFFFFu, m, off));
    if ((tid & 31) == 0) red[tid >> 5] = m;
    __syncthreads();
    if (tid == 0) {
        float mm = red[0];
#pragma unroll
        for (int w = 1; w < 8; w++) mm = fmaxf(mm, red[w]);
        s_bval = mm;
    }
    __syncthreads();
    m = s_bval;

    // exp + sum over kept
    float sum = 0.0f;
    for (int i = tid; i < L; i += 256) {
        float v = sc[i];
        float e = (v >= thresh) ? __expf(v - m) : 0.0f;
        sc[i] = e;
        sum += e;
    }
#pragma unroll
    for (int off = 16; off; off >>= 1) sum += __shfl_xor_sync(0xFFFFFFFFu, sum, off);
    if ((tid & 31) == 0) red[tid >> 5] = sum;
    __syncthreads();
    if (tid == 0) {
        float ss = 0.0f;
#pragma unroll
        for (int w = 0; w < 8; w++) ss += red[w];
        s_bval = ss;
    }
    __syncthreads();
    float inv = 1.0f / s_bval;

    for (int i = tid; i < L; i += 256) g_P[base + i] = sc[i] * inv;
    // zero diagonal-tile tail so AV GEMM can be dense over lower tiles
    int tileEnd = ((q >> 6) + 1) << 6;
    for (int i = L + tid; i < tileEnd; i += 256) g_P[base + i] = 0.0f;
}

// ---------------- K4: O = P @ V  (lower-triangular tiles only) ---------------
__global__ void av_kernel()
{
    int qt = blockIdx.x;
    int bh = blockIdx.y;

    __shared__ float Ps[64][68];
    __shared__ float Vs[64][68];

    int tid = threadIdx.x;
    int tx = tid & 15;
    int ty = tid >> 4;

    float acc[4][4];
#pragma unroll
    for (int i = 0; i < 4; i++)
#pragma unroll
        for (int j = 0; j < 4; j++) acc[i][j] = 0.0f;

    for (int kt = 0; kt <= qt; kt++) {
        const float* Pg = &g_P[((size_t)bh * SEQ + qt * 64) * SEQ + kt * 64];
        const float* Vg = &g_V[((size_t)bh * SEQ + kt * 64) * HDIM];
#pragma unroll
        for (int t = 0; t < 4; t++) {
            int v = tid + t * 256;
            int r = v >> 4;
            int c4 = (v & 15) * 4;
            *(float4*)&Ps[r][c4] = *(const float4*)&Pg[(size_t)r * SEQ + c4];
            *(float4*)&Vs[r][c4] = *(const float4*)&Vg[(size_t)r * HDIM + c4];
        }
        __syncthreads();
#pragma unroll 8
        for (int kk = 0; kk < 64; kk++) {
            float a[4], b[4];
#pragma unroll
            for (int i = 0; i < 4; i++) a[i] = Ps[ty * 4 + i][kk];
#pragma unroll
            for (int j = 0; j < 4; j++) b[j] = Vs[kk][tx * 4 + j];
#pragma unroll
            for (int i = 0; i < 4; i++)
#pragma unroll
                for (int j = 0; j < 4; j++) acc[i][j] = fmaf(a[i], b[j], acc[i][j]);
        }
        __syncthreads();
    }

    int b = bh / NHEADS;
    int h = bh - b * NHEADS;
#pragma unroll
    for (int i = 0; i < 4; i++) {
        int q = qt * 64 + ty * 4 + i;
        float4 o;
        o.x = acc[i][0]; o.y = acc[i][1]; o.z = acc[i][2]; o.w = acc[i][3];
        *(float4*)&g_O[(size_t)(b * SEQ + q) * DMODEL + h * HDIM + tx * 4] = o;
    }
}

// ---------------- launch ------------------------------------------------------
extern "C" void kernel_launch(void* const* d_in, const int* in_sizes, int n_in,
                              void* d_out, int out_size)
{
    const float* h_ssm = (const float*)d_in[0];
    const float* gate  = (const float*)d_in[1];
    const float* Wq = (const float*)d_in[2];
    const float* bq = (const float*)d_in[3];
    const float* Wk = (const float*)d_in[4];
    const float* bk = (const float*)d_in[5];
    const float* Wv = (const float*)d_in[6];
    const float* bv = (const float*)d_in[7];
    const float* Wo = (const float*)d_in[8];
    const float* bo = (const float*)d_in[9];
    float* out = (float*)d_out;

    dim3 gProj(DMODEL / 128, NROWS / 128);          // (8, 32)
    gemm_kernel<<<gProj, 256>>>(h_ssm, Wq, bq, nullptr, nullptr, 0);
    gemm_kernel<<<gProj, 256>>>(h_ssm, Wk, bk, nullptr, nullptr, 1);
    gemm_kernel<<<gProj, 256>>>(h_ssm, Wv, bv, nullptr, nullptr, 2);

    scores_kernel<<<dim3(SEQ / 64, SEQ / 64, BH), 256>>>();
    topk_softmax_kernel<<<dim3(BH * SEQ), 256>>>();
    av_kernel<<<dim3(SEQ / 64, BH), 256>>>();

    gemm_kernel<<<gProj, 256>>>(nullptr, Wo, bo, out, gate, 3);
}

// round 2
// speedup vs baseline: 1.2838x; 1.2838x over previous
#include <cuda_runtime.h>
#include <cuda_bf16.h>
#include <math.h>
#include <stdint.h>

// Problem constants
#define BATCH 2
#define SEQ 2048
#define DMODEL 1024
#define NHEADS 16
#define HDIM 64
#define TOPK 64
#define NROWS (BATCH * SEQ)          // 4096
#define BH (BATCH * NHEADS)          // 32

// ---------------- scratch (device globals; allocation-free rule) -------------
__device__ float g_Q[(size_t)BH * SEQ * HDIM];   // [bh, s, d] 16MB
__device__ float g_K[(size_t)BH * SEQ * HDIM];   // 16MB
__device__ float g_V[(size_t)BH * SEQ * HDIM];   // 16MB
__device__ float g_P[(size_t)BH * SEQ * SEQ];    // scores -> probs, 512MB
__device__ float g_O[(size_t)NROWS * DMODEL];    // attn output pre-Wo, 16MB

// ---------------- K1/K5: 128x128x16 SGEMM, double-buffered prefetch ----------
// mode 0/1/2: out = h_ssm @ W + b written into g_Q/g_K/g_V in [b,h,s,d] layout
// mode 3:     out = g_O @ Wo + bo, scaled by gate[row], written to d_out
__global__ __launch_bounds__(256) void gemm_kernel(
    const float* __restrict__ A,
    const float* __restrict__ W,
    const float* __restrict__ bias,
    float* __restrict__ outp,
    const float* __restrict__ gate,
    int mode)
{
    __shared__ float As[16][132];
    __shared__ float Bs[16][128];

    const int K = DMODEL;
    const int NC = DMODEL;
    int tid = threadIdx.x;
    int tx = tid & 15;         // 0..15
    int ty = tid >> 4;         // 0..15
    int rowTile = blockIdx.y * 128;
    int colTile = blockIdx.x * 128;

    const float* Ap = (mode == 3) ? g_O : A;
    float* Op = (mode == 0) ? g_Q : (mode == 1) ? g_K : (mode == 2) ? g_V : outp;

    int ar = tid >> 1;               // 0..127
    int ac8 = (tid & 1) * 8;         // 0 or 8
    int br = tid >> 4;               // 0..15
    int bc8 = (tid & 15) * 8;        // 0..120

    float acc[8][8];
#pragma unroll
    for (int i = 0; i < 8; i++)
#pragma unroll
        for (int j = 0; j < 8; j++) acc[i][j] = 0.0f;

    const float* aptr = &Ap[(size_t)(rowTile + ar) * K];
    const float* bptr = &W[(size_t)colTile + bc8];

    // load slab 0 to smem
    {
        float4 a0 = *(const float4*)&aptr[ac8 + 0];
        float4 a1 = *(const float4*)&aptr[ac8 + 4];
        As[ac8 + 0][ar] = a0.x; As[ac8 + 1][ar] = a0.y;
        As[ac8 + 2][ar] = a0.z; As[ac8 + 3][ar] = a0.w;
        As[ac8 + 4][ar] = a1.x; As[ac8 + 5][ar] = a1.y;
        As[ac8 + 6][ar] = a1.z; As[ac8 + 7][ar] = a1.w;
        float4 b0 = *(const float4*)&bptr[(size_t)br * NC + 0];
        float4 b1 = *(const float4*)&bptr[(size_t)br * NC + 4];
        *(float4*)&Bs[br][bc8 + 0] = b0;
        *(float4*)&Bs[br][bc8 + 4] = b1;
    }
    __syncthreads();

    for (int k0 = 0; k0 < K; k0 += 16) {
        bool has = (k0 + 16) < K;
        float4 pa0, pa1, pb0, pb1;
        if (has) {
            pa0 = *(const float4*)&aptr[k0 + 16 + ac8 + 0];
            pa1 = *(const float4*)&aptr[k0 + 16 + ac8 + 4];
            pb0 = *(const float4*)&bptr[(size_t)(k0 + 16 + br) * NC + 0];
            pb1 = *(const float4*)&bptr[(size_t)(k0 + 16 + br) * NC + 4];
        }
#pragma unroll
        for (int kk = 0; kk < 16; kk++) {
            float a[8], b[8];
            *(float4*)&a[0] = *(const float4*)&As[kk][ty * 8 + 0];
            *(float4*)&a[4] = *(const float4*)&As[kk][ty * 8 + 4];
            *(float4*)&b[0] = *(const float4*)&Bs[kk][tx * 8 + 0];
            *(float4*)&b[4] = *(const float4*)&Bs[kk][tx * 8 + 4];
#pragma unroll
            for (int i = 0; i < 8; i++)
#pragma unroll
                for (int j = 0; j < 8; j++) acc[i][j] = fmaf(a[i], b[j], acc[i][j]);
        }
        __syncthreads();
        if (has) {
            As[ac8 + 0][ar] = pa0.x; As[ac8 + 1][ar] = pa0.y;
            As[ac8 + 2][ar] = pa0.z; As[ac8 + 3][ar] = pa0.w;
            As[ac8 + 4][ar] = pa1.x; As[ac8 + 5][ar] = pa1.y;
            As[ac8 + 6][ar] = pa1.z; As[ac8 + 7][ar] = pa1.w;
            *(float4*)&Bs[br][bc8 + 0] = pb0;
            *(float4*)&Bs[br][bc8 + 4] = pb1;
            __syncthreads();
        }
    }

#pragma unroll
    for (int i = 0; i < 8; i++) {
        int m = rowTile + ty * 8 + i;
#pragma unroll
        for (int j = 0; j < 8; j++) {
            int n = colTile + tx * 8 + j;
            float v = acc[i][j] + bias[n];
            if (mode < 3) {
                int b = m / SEQ;
                int s = m - b * SEQ;
                int h = n >> 6;
                int d = n & 63;
                Op[((size_t)(b * NHEADS + h) * SEQ + s) * HDIM + d] = v;
            } else {
                Op[(size_t)m * DMODEL + n] = v * gate[m];
            }
        }
    }
}

// ---------------- K2: scores = Q K^T / 8, causal, 128x128 tiles --------------
__global__ __launch_bounds__(256) void scores_kernel()
{
    int kt = blockIdx.x;
    int qt = blockIdx.y;
    int bh = blockIdx.z;
    if (kt > qt) return;

    __shared__ float Qs[32][132];  // [d][row]
    __shared__ float Ks[32][132];  // [d][col]

    int tid = threadIdx.x;
    int tx = tid & 15;
    int ty = tid >> 4;
    const float* Qg = &g_Q[((size_t)bh * SEQ + qt * 128) * HDIM];
    const float* Kg = &g_K[((size_t)bh * SEQ + kt * 128) * HDIM];

    float acc[8][8];
#pragma unroll
    for (int i = 0; i < 8; i++)
#pragma unroll
        for (int j = 0; j < 8; j++) acc[i][j] = 0.0f;

    int lr = tid >> 1;            // 0..127 row
    int lc = (tid & 1) * 16;      // 0 or 16 within 32-slab

    for (int d0 = 0; d0 < HDIM; d0 += 32) {
#pragma unroll
        for (int t = 0; t < 4; t++) {
            float4 qv = *(const float4*)&Qg[(size_t)lr * HDIM + d0 + lc + t * 4];
            Qs[lc + t * 4 + 0][lr] = qv.x; Qs[lc + t * 4 + 1][lr] = qv.y;
            Qs[lc + t * 4 + 2][lr] = qv.z; Qs[lc + t * 4 + 3][lr] = qv.w;
            float4 kv = *(const float4*)&Kg[(size_t)lr * HDIM + d0 + lc + t * 4];
            Ks[lc + t * 4 + 0][lr] = kv.x; Ks[lc + t * 4 + 1][lr] = kv.y;
            Ks[lc + t * 4 + 2][lr] = kv.z; Ks[lc + t * 4 + 3][lr] = kv.w;
        }
        __syncthreads();
#pragma unroll
        for (int kk = 0; kk < 32; kk++) {
            float a[8], b[8];
            *(float4*)&a[0] = *(const float4*)&Qs[kk][ty * 8 + 0];
            *(float4*)&a[4] = *(const float4*)&Qs[kk][ty * 8 + 4];
            *(float4*)&b[0] = *(const float4*)&Ks[kk][tx * 8 + 0];
            *(float4*)&b[4] = *(const float4*)&Ks[kk][tx * 8 + 4];
#pragma unroll
            for (int i = 0; i < 8; i++)
#pragma unroll
                for (int j = 0; j < 8; j++) acc[i][j] = fmaf(a[i], b[j], acc[i][j]);
        }
        __syncthreads();
    }

    const float scale = 0.125f;  // 1/sqrt(64)
    bool diag = (kt == qt);
#pragma unroll
    for (int i = 0; i < 8; i++) {
        int q = qt * 128 + ty * 8 + i;
        int kbase = kt * 128 + tx * 8;
        float vv[8];
#pragma unroll
        for (int j = 0; j < 8; j++) {
            float s = acc[i][j] * scale;
            vv[j] = (diag && (kbase + j > q)) ? -INFINITY : s;
        }
        float* dst = &g_P[((size_t)bh * SEQ + q) * SEQ + kbase];
        *(float4*)&dst[0] = *(float4*)&vv[0];
        *(float4*)&dst[4] = *(float4*)&vv[4];
    }
}

// ---------------- K3: exact top-64 threshold + masked softmax ----------------
// Per-warp radix histograms + parallel suffix-scan bin select.
__global__ __launch_bounds__(256) void topk_softmax_kernel()
{
    int row = blockIdx.x;             // 0 .. BH*SEQ-1
    int bh = row >> 11;               // /SEQ
    int q = row & (SEQ - 1);
    size_t base = ((size_t)bh * SEQ + q) * SEQ;
    int L = q + 1;
    int tid = threadIdx.x;
    int lane = tid & 31;
    int warp = tid >> 5;

    __shared__ float sc[SEQ];
    __shared__ unsigned hist[8][256];
    __shared__ unsigned sufS[256];
    __shared__ unsigned cntS[256];
    __shared__ unsigned warpTot[8];
    __shared__ unsigned ballots[8];
    __shared__ unsigned s_prefix;
    __shared__ int s_kk;
    __shared__ float red[8];
    __shared__ float s_bval;

    for (int i = tid; i < L; i += 256) sc[i] = g_P[base + i];
    if (tid == 0) s_kk = TOPK;
    __syncthreads();

    float thresh = -INFINITY;
    if (L > TOPK) {
        unsigned prefix = 0, himask = 0;
        int kk = TOPK;
        for (int p = 24; p >= 0; p -= 8) {
            // zero per-warp histograms
            for (int i = tid; i < 8 * 256; i += 256) ((unsigned*)hist)[i] = 0;
            __syncthreads();
            for (int i = tid; i < L; i += 256) {
                unsigned u = __float_as_uint(sc[i]);
                unsigned key = (u & 0x80000000u) ? ~u : (u | 0x80000000u);
                if ((key & himask) == prefix)
                    atomicAdd(&hist[warp][(key >> p) & 0xFFu], 1u);
            }
            __syncthreads();
            // reduce 8 warps' bins; thread tid owns bin tid
            unsigned cnt = 0;
#pragma unroll
            for (int w = 0; w < 8; w++) cnt += hist[w][tid];
            // suffix sum within warp (bins tid covers warp*32..warp*32+31)
            unsigned s = cnt;
#pragma unroll
            for (int off = 1; off < 32; off <<= 1) {
                unsigned t = __shfl_down_sync(0xFFFFFFFFu, s, off);
                if (lane + off < 32) s += t;
            }
            if (lane == 0) warpTot[warp] = s;
            __syncthreads();
            unsigned hi = 0;
            for (int w2 = warp + 1; w2 < 8; w2++) hi += warpTot[w2];
            unsigned S = s + hi;        // suffix over all bins >= tid
            sufS[tid] = S;
            cntS[tid] = cnt;
            unsigned bal = __ballot_sync(0xFFFFFFFFu, S >= (unsigned)kk);
            if (lane == 0) ballots[warp] = bal;
            __syncthreads();
            if (tid == 0) {
                int sel = 0;
                for (int w = 7; w >= 0; w--) {
                    if (ballots[w]) { sel = w * 32 + (31 - __clz(ballots[w])); break; }
                }
                s_kk = s_kk - (int)(sufS[sel] - cntS[sel]);
                s_prefix = prefix | ((unsigned)sel << p);
            }
            __syncthreads();
            prefix = s_prefix;
            kk = s_kk;
            himask |= (0xFFu << p);
            __syncthreads();
        }
        unsigned key = prefix;
        unsigned u = (key & 0x80000000u) ? (key & 0x7FFFFFFFu) : ~key;
        thresh = __uint_as_float(u);
    }

    // row max (max element is always kept)
    float m = -INFINITY;
    for (int i = tid; i < L; i += 256) m = fmaxf(m, sc[i]);
#pragma unroll
    for (int off = 16; off; off >>= 1) m = fmaxf(m, __shfl_xor_sync(0xFFFFFFFFu, m, off));
    if (lane == 0) red[warp] = m;
    __syncthreads();
    if (tid == 0) {
        float mm = red[0];
#pragma unroll
        for (int w = 1; w < 8; w++) mm = fmaxf(mm, red[w]);
        s_bval = mm;
    }
    __syncthreads();
    m = s_bval;

    // exp + sum over kept
    float sum = 0.0f;
    for (int i = tid; i < L; i += 256) {
        float v = sc[i];
        float e = (v >= thresh) ? __expf(v - m) : 0.0f;
        sc[i] = e;
        sum += e;
    }
#pragma unroll
    for (int off = 16; off; off >>= 1) sum += __shfl_xor_sync(0xFFFFFFFFu, sum, off);
    if (lane == 0) red[warp] = sum;
    __syncthreads();
    if (tid == 0) {
        float ss = 0.0f;
#pragma unroll
        for (int w = 0; w < 8; w++) ss += red[w];
        s_bval = ss;
    }
    __syncthreads();
    float inv = 1.0f / s_bval;

    for (int i = tid; i < L; i += 256) g_P[base + i] = sc[i] * inv;
    // zero diagonal-tile tail (to 128 boundary) so AV GEMM can stay dense
    int tileEnd = ((q >> 7) + 1) << 7;
    for (int i = L + tid; i < tileEnd; i += 256) g_P[base + i] = 0.0f;
}

// ---------------- K4: O = P @ V  (128q x 64d tiles, 8x8 micro) ---------------
__global__ __launch_bounds__(128) void av_kernel()
{
    int qt = blockIdx.x;   // 0..15
    int bh = blockIdx.y;

    __shared__ float PsT[32][132];   // [k][q]
    __shared__ float Vs[32][68];     // [k][d]

    int tid = threadIdx.x;           // 0..127
    int tx = tid & 7;                // 0..7  (d groups)
    int ty = tid >> 3;               // 0..15 (q groups)

    float acc[8][8];
#pragma unroll
    for (int i = 0; i < 8; i++)
#pragma unroll
        for (int j = 0; j < 8; j++) acc[i][j] = 0.0f;

    int nk = (qt + 1) * 128;
    const float* Prow = &g_P[((size_t)bh * SEQ + qt * 128 + tid) * SEQ];
    int vr = tid >> 2;               // 0..31
    int vc = (tid & 3) * 16;         // 0..48

    for (int kbase = 0; kbase < nk; kbase += 32) {
        // P block transpose: thread tid owns q-row tid, cols kbase..kbase+31
#pragma unroll
        for (int t = 0; t < 8; t++) {
            float4 pv = *(const float4*)&Prow[kbase + t * 4];
            PsT[t * 4 + 0][tid] = pv.x; PsT[t * 4 + 1][tid] = pv.y;
            PsT[t * 4 + 2][tid] = pv.z; PsT[t * 4 + 3][tid] = pv.w;
        }
        const float* Vg = &g_V[((size_t)bh * SEQ + kbase + vr) * HDIM + vc];
#pragma unroll
        for (int t = 0; t < 4; t++)
            *(float4*)&Vs[vr][vc + t * 4] = *(const float4*)&Vg[t * 4];
        __syncthreads();
#pragma unroll
        for (int kk = 0; kk < 32; kk++) {
            float a[8], b[8];
            *(float4*)&a[0] = *(const float4*)&PsT[kk][ty * 8 + 0];
            *(float4*)&a[4] = *(const float4*)&PsT[kk][ty * 8 + 4];
            *(float4*)&b[0] = *(const float4*)&Vs[kk][tx * 8 + 0];
            *(float4*)&b[4] = *(const float4*)&Vs[kk][tx * 8 + 4];
#pragma unroll
            for (int i = 0; i < 8; i++)
#pragma unroll
                for (int j = 0; j < 8; j++) acc[i][j] = fmaf(a[i], b[j], acc[i][j]);
        }
        __syncthreads();
    }

    int b = bh / NHEADS;
    int h = bh - b * NHEADS;
#pragma unroll
    for (int i = 0; i < 8; i++) {
        int qq = qt * 128 + ty * 8 + i;
        float* dst = &g_O[(size_t)(b * SEQ + qq) * DMODEL + h * HDIM + tx * 8];
        *(float4*)&dst[0] = *(float4*)&acc[i][0];
        *(float4*)&dst[4] = *(float4*)&acc[i][4];
    }
}

// ---------------- launch ------------------------------------------------------
extern "C" void kernel_launch(void* const* d_in, const int* in_sizes, int n_in,
                              void* d_out, int out_size)
{
    const float* h_ssm = (const float*)d_in[0];
    const float* gate  = (const float*)d_in[1];
    const float* Wq = (const float*)d_in[2];
    const float* bq = (const float*)d_in[3];
    const float* Wk = (const float*)d_in[4];
    const float* bk = (const float*)d_in[5];
    const float* Wv = (const float*)d_in[6];
    const float* bv = (const float*)d_in[7];
    const float* Wo = (const float*)d_in[8];
    const float* bo = (const float*)d_in[9];
    float* out = (float*)d_out;

    dim3 gProj(DMODEL / 128, NROWS / 128);          // (8, 32)
    gemm_kernel<<<gProj, 256>>>(h_ssm, Wq, bq, nullptr, nullptr, 0);
    gemm_kernel<<<gProj, 256>>>(h_ssm, Wk, bk, nullptr, nullptr, 1);
    gemm_kernel<<<gProj, 256>>>(h_ssm, Wv, bv, nullptr, nullptr, 2);

    scores_kernel<<<dim3(SEQ / 128, SEQ / 128, BH), 256>>>();
    topk_softmax_kernel<<<dim3(BH * SEQ), 256>>>();
    av_kernel<<<dim3(SEQ / 128, BH), 128>>>();

    gemm_kernel<<<gProj, 256>>>(nullptr, Wo, bo, out, gate, 3);
}

// round 4
// speedup vs baseline: 1.6068x; 1.2516x over previous
#include <cuda_runtime.h>
#include <cuda_bf16.h>
#include <math.h>
#include <stdint.h>

// Problem constants
#define BATCH 2
#define SEQ 2048
#define DMODEL 1024
#define NHEADS 16
#define HDIM 64
#define TOPK 64
#define NROWS (BATCH * SEQ)          // 4096
#define BH (BATCH * NHEADS)          // 32

// ---------------- scratch (device globals; allocation-free rule) -------------
__device__ float g_Q[(size_t)BH * SEQ * HDIM];   // [bh, s, d] 16MB
__device__ float g_K[(size_t)BH * SEQ * HDIM];   // 16MB
__device__ float g_V[(size_t)BH * SEQ * HDIM];   // 16MB
__device__ float g_P[(size_t)BH * SEQ * SEQ];    // scores -> probs, 512MB
__device__ float g_O[(size_t)NROWS * DMODEL];    // attn output pre-Wo, 16MB

// ---------------- tensor-core helpers ----------------------------------------
__device__ __forceinline__ uint32_t smem_u32(const void* p) {
    return (uint32_t)__cvta_generic_to_shared(p);
}
__device__ __forceinline__ void ldmA4(uint32_t addr, uint32_t& r0, uint32_t& r1,
                                      uint32_t& r2, uint32_t& r3) {
    asm volatile("ldmatrix.sync.aligned.m8n8.x4.shared.b16 {%0,%1,%2,%3}, [%4];"
                 : "=r"(r0), "=r"(r1), "=r"(r2), "=r"(r3) : "r"(addr));
}
__device__ __forceinline__ void ldmB2t(uint32_t addr, uint32_t& r0, uint32_t& r1) {
    asm volatile("ldmatrix.sync.aligned.m8n8.x2.trans.shared.b16 {%0,%1}, [%2];"
                 : "=r"(r0), "=r"(r1) : "r"(addr));
}
__device__ __forceinline__ void mma16816(float* c, uint32_t a0, uint32_t a1,
                                         uint32_t a2, uint32_t a3,
                                         uint32_t b0, uint32_t b1) {
    asm volatile(
        "mma.sync.aligned.m16n8k16.row.col.f32.bf16.bf16.f32 "
        "{%0,%1,%2,%3}, {%4,%5,%6,%7}, {%8,%9}, {%0,%1,%2,%3};"
        : "+f"(c[0]), "+f"(c[1]), "+f"(c[2]), "+f"(c[3])
        : "r"(a0), "r"(a1), "r"(a2), "r"(a3), "r"(b0), "r"(b1));
}
__device__ __forceinline__ void split_bf16(float x, __nv_bfloat16& hi, __nv_bfloat16& lo) {
    hi = __float2bfloat16(x);
    lo = __float2bfloat16(x - __bfloat162float(hi));
}

// ---------------- K1: 128x128x16 fp32 SGEMM (Q/K projections only) -----------
__global__ __launch_bounds__(256) void gemm_kernel(
    const float* __restrict__ A,
    const float* __restrict__ W,
    const float* __restrict__ bias,
    int mode)   // 0 -> g_Q, 1 -> g_K
{
    __shared__ float As[16][132];
    __shared__ float Bs[16][128];

    const int K = DMODEL;
    const int NC = DMODEL;
    int tid = threadIdx.x;
    int tx = tid & 15;
    int ty = tid >> 4;
    int rowTile = blockIdx.y * 128;
    int colTile = blockIdx.x * 128;

    float* Op = (mode == 0) ? g_Q : g_K;

    int ar = tid >> 1;
    int ac8 = (tid & 1) * 8;
    int br = tid >> 4;
    int bc8 = (tid & 15) * 8;

    float acc[8][8];
#pragma unroll
    for (int i = 0; i < 8; i++)
#pragma unroll
        for (int j = 0; j < 8; j++) acc[i][j] = 0.0f;

    const float* aptr = &A[(size_t)(rowTile + ar) * K];
    const float* bptr = &W[(size_t)colTile + bc8];

    {
        float4 a0 = *(const float4*)&aptr[ac8 + 0];
        float4 a1 = *(const float4*)&aptr[ac8 + 4];
        As[ac8 + 0][ar] = a0.x; As[ac8 + 1][ar] = a0.y;
        As[ac8 + 2][ar] = a0.z; As[ac8 + 3][ar] = a0.w;
        As[ac8 + 4][ar] = a1.x; As[ac8 + 5][ar] = a1.y;
        As[ac8 + 6][ar] = a1.z; As[ac8 + 7][ar] = a1.w;
        *(float4*)&Bs[br][bc8 + 0] = *(const float4*)&bptr[(size_t)br * NC + 0];
        *(float4*)&Bs[br][bc8 + 4] = *(const float4*)&bptr[(size_t)br * NC + 4];
    }
    __syncthreads();

    for (int k0 = 0; k0 < K; k0 += 16) {
        bool has = (k0 + 16) < K;
        float4 pa0, pa1, pb0, pb1;
        if (has) {
            pa0 = *(const float4*)&aptr[k0 + 16 + ac8 + 0];
            pa1 = *(const float4*)&aptr[k0 + 16 + ac8 + 4];
            pb0 = *(const float4*)&bptr[(size_t)(k0 + 16 + br) * NC + 0];
            pb1 = *(const float4*)&bptr[(size_t)(k0 + 16 + br) * NC + 4];
        }
#pragma unroll
        for (int kk = 0; kk < 16; kk++) {
            float a[8], b[8];
            *(float4*)&a[0] = *(const float4*)&As[kk][ty * 8 + 0];
            *(float4*)&a[4] = *(const float4*)&As[kk][ty * 8 + 4];
            *(float4*)&b[0] = *(const float4*)&Bs[kk][tx * 8 + 0];
            *(float4*)&b[4] = *(const float4*)&Bs[kk][tx * 8 + 4];
#pragma unroll
            for (int i = 0; i < 8; i++)
#pragma unroll
                for (int j = 0; j < 8; j++) acc[i][j] = fmaf(a[i], b[j], acc[i][j]);
        }
        __syncthreads();
        if (has) {
            As[ac8 + 0][ar] = pa0.x; As[ac8 + 1][ar] = pa0.y;
            As[ac8 + 2][ar] = pa0.z; As[ac8 + 3][ar] = pa0.w;
            As[ac8 + 4][ar] = pa1.x; As[ac8 + 5][ar] = pa1.y;
            As[ac8 + 6][ar] = pa1.z; As[ac8 + 7][ar] = pa1.w;
            *(float4*)&Bs[br][bc8 + 0] = pb0;
            *(float4*)&Bs[br][bc8 + 4] = pb1;
            __syncthreads();
        }
    }

#pragma unroll
    for (int i = 0; i < 8; i++) {
        int m = rowTile + ty * 8 + i;
        int b = m / SEQ;
        int s = m - b * SEQ;
#pragma unroll
        for (int j = 0; j < 8; j++) {
            int n = colTile + tx * 8 + j;
            int h = n >> 6;
            int d = n & 63;
            Op[((size_t)(b * NHEADS + h) * SEQ + s) * HDIM + d] = acc[i][j] + bias[n];
        }
    }
}

// ---------------- K1b: 128x128 split-bf16 tensor-core GEMM -------------------
// mode 2: g_V = h_ssm @ Wv + bv   ([b,h,s,d] layout)
// mode 3: out = (g_O @ Wo + bo) * gate
__global__ __launch_bounds__(256) void gemm_bf16_kernel(
    const float* __restrict__ A,
    const float* __restrict__ W,
    const float* __restrict__ bias,
    float* __restrict__ outp,
    const float* __restrict__ gate,
    int mode)
{
    __shared__ __nv_bfloat16 Ahi[128][40], Alo[128][40];
    __shared__ __nv_bfloat16 Bhi[32][136], Blo[32][136];

    const int K = DMODEL;
    const int NC = DMODEL;
    int tid = threadIdx.x;
    int lane = tid & 31;
    int wid = tid >> 5;
    int wm = wid & 1;            // 2 warp rows (64 rows each)
    int wn = wid >> 1;           // 4 warp cols (32 cols each)
    int rowTile = blockIdx.y * 128;
    int colTile = blockIdx.x * 128;

    const float* Ap = (mode == 3) ? g_O : A;

    int ar = tid >> 1, ac = (tid & 1) * 16;
    int br = tid >> 3, bc = (tid & 7) * 16;
    const float* aptr = &Ap[(size_t)(rowTile + ar) * K + ac];
    const float* bptr = &W[(size_t)br * NC + colTile + bc];

    float acc[4][4][4];
#pragma unroll
    for (int mi = 0; mi < 4; mi++)
#pragma unroll
        for (int ni = 0; ni < 4; ni++)
#pragma unroll
            for (int r = 0; r < 4; r++) acc[mi][ni][r] = 0.0f;

    float4 pa[4], pb[4];
#pragma unroll
    for (int t = 0; t < 4; t++) {
        pa[t] = *(const float4*)&aptr[t * 4];
        pb[t] = *(const float4*)&bptr[t * 4];
    }
    // convert + store slab 0
#pragma unroll
    for (int t = 0; t < 4; t++) {
        float v[4] = {pa[t].x, pa[t].y, pa[t].z, pa[t].w};
        __nv_bfloat16 h0, l0, h1, l1;
        split_bf16(v[0], h0, l0); split_bf16(v[1], h1, l1);
        *(__nv_bfloat162*)&Ahi[ar][ac + t * 4] = __nv_bfloat162(h0, h1);
        *(__nv_bfloat162*)&Alo[ar][ac + t * 4] = __nv_bfloat162(l0, l1);
        split_bf16(v[2], h0, l0); split_bf16(v[3], h1, l1);
        *(__nv_bfloat162*)&Ahi[ar][ac + t * 4 + 2] = __nv_bfloat162(h0, h1);
        *(__nv_bfloat162*)&Alo[ar][ac + t * 4 + 2] = __nv_bfloat162(l0, l1);
        float w[4] = {pb[t].x, pb[t].y, pb[t].z, pb[t].w};
        split_bf16(w[0], h0, l0); split_bf16(w[1], h1, l1);
        *(__nv_bfloat162*)&Bhi[br][bc + t * 4] = __nv_bfloat162(h0, h1);
        *(__nv_bfloat162*)&Blo[br][bc + t * 4] = __nv_bfloat162(l0, l1);
        split_bf16(w[2], h0, l0); split_bf16(w[3], h1, l1);
        *(__nv_bfloat162*)&Bhi[br][bc + t * 4 + 2] = __nv_bfloat162(h0, h1);
        *(__nv_bfloat162*)&Blo[br][bc + t * 4 + 2] = __nv_bfloat162(l0, l1);
    }
    __syncthreads();

    for (int s = 0; s < K / 32; s++) {
        bool has = (s + 1) < K / 32;
        if (has) {
            int k0 = (s + 1) * 32;
#pragma unroll
            for (int t = 0; t < 4; t++) {
                pa[t] = *(const float4*)&aptr[k0 + t * 4];
                pb[t] = *(const float4*)&bptr[(size_t)k0 * NC + t * 4];
            }
        }
#pragma unroll
        for (int ks = 0; ks < 2; ks++) {
            int kk = ks * 16;
            uint32_t bhr[4][2], blr[4][2];
#pragma unroll
            for (int ni = 0; ni < 4; ni++) {
                ldmB2t(smem_u32(&Bhi[kk + (lane & 15)][wn * 32 + ni * 8]), bhr[ni][0], bhr[ni][1]);
                ldmB2t(smem_u32(&Blo[kk + (lane & 15)][wn * 32 + ni * 8]), blr[ni][0], blr[ni][1]);
            }
#pragma unroll
            for (int mi = 0; mi < 4; mi++) {
                int arow = wm * 64 + mi * 16 + (lane & 15);
                int acol = kk + ((lane >> 4) << 3);
                uint32_t ah0, ah1, ah2, ah3, al0, al1, al2, al3;
                ldmA4(smem_u32(&Ahi[arow][acol]), ah0, ah1, ah2, ah3);
                ldmA4(smem_u32(&Alo[arow][acol]), al0, al1, al2, al3);
#pragma unroll
                for (int ni = 0; ni < 4; ni++) {
                    mma16816(acc[mi][ni], ah0, ah1, ah2, ah3, bhr[ni][0], bhr[ni][1]);
                    mma16816(acc[mi][ni], al0, al1, al2, al3, bhr[ni][0], bhr[ni][1]);
                    mma16816(acc[mi][ni], ah0, ah1, ah2, ah3, blr[ni][0], blr[ni][1]);
                }
            }
        }
        __syncthreads();
        if (has) {
#pragma unroll
            for (int t = 0; t < 4; t++) {
                float v[4] = {pa[t].x, pa[t].y, pa[t].z, pa[t].w};
                __nv_bfloat16 h0, l0, h1, l1;
                split_bf16(v[0], h0, l0); split_bf16(v[1], h1, l1);
                *(__nv_bfloat162*)&Ahi[ar][ac + t * 4] = __nv_bfloat162(h0, h1);
                *(__nv_bfloat162*)&Alo[ar][ac + t * 4] = __nv_bfloat162(l0, l1);
                split_bf16(v[2], h0, l0); split_bf16(v[3], h1, l1);
                *(__nv_bfloat162*)&Ahi[ar][ac + t * 4 + 2] = __nv_bfloat162(h0, h1);
                *(__nv_bfloat162*)&Alo[ar][ac + t * 4 + 2] = __nv_bfloat162(l0, l1);
                float w[4] = {pb[t].x, pb[t].y, pb[t].z, pb[t].w};
                split_bf16(w[0], h0, l0); split_bf16(w[1], h1, l1);
                *(__nv_bfloat162*)&Bhi[br][bc + t * 4] = __nv_bfloat162(h0, h1);
                *(__nv_bfloat162*)&Blo[br][bc + t * 4] = __nv_bfloat162(l0, l1);
                split_bf16(w[2], h0, l0); split_bf16(w[3], h1, l1);
                *(__nv_bfloat162*)&Bhi[br][bc + t * 4 + 2] = __nv_bfloat162(h0, h1);
                *(__nv_bfloat162*)&Blo[br][bc + t * 4 + 2] = __nv_bfloat162(l0, l1);
            }
            __syncthreads();
        }
    }

    // epilogue
#pragma unroll
    for (int mi = 0; mi < 4; mi++) {
#pragma unroll
        for (int ni = 0; ni < 4; ni++) {
            int row0 = rowTile + wm * 64 + mi * 16 + (lane >> 2);
            int col0 = colTile + wn * 32 + ni * 8 + (lane & 3) * 2;
            float b0 = bias[col0], b1 = bias[col0 + 1];
#pragma unroll
            for (int half = 0; half < 2; half++) {
                int m = row0 + half * 8;
                float v0 = acc[mi][ni][half * 2 + 0] + b0;
                float v1 = acc[mi][ni][half * 2 + 1] + b1;
                if (mode == 2) {
                    int b = m / SEQ;
                    int ss = m - b * SEQ;
                    int h = col0 >> 6;
                    int d = col0 & 63;
                    float2* dst = (float2*)&g_V[((size_t)(b * NHEADS + h) * SEQ + ss) * HDIM + d];
                    *dst = make_float2(v0, v1);
                } else {
                    float gm = gate[m];
                    float2* dst = (float2*)&outp[(size_t)m * DMODEL + col0];
                    *dst = make_float2(v0 * gm, v1 * gm);
                }
            }
        }
    }
}

// ---------------- K2: scores = Q K^T / 8, causal, 128x128, fp32 --------------
__global__ __launch_bounds__(256) void scores_kernel()
{
    int kt = blockIdx.x;
    int qt = blockIdx.y;
    int bh = blockIdx.z;
    if (kt > qt) return;

    __shared__ float Qs[32][132];
    __shared__ float Ks[32][132];

    int tid = threadIdx.x;
    int tx = tid & 15;
    int ty = tid >> 4;
    const float* Qg = &g_Q[((size_t)bh * SEQ + qt * 128) * HDIM];
    const float* Kg = &g_K[((size_t)bh * SEQ + kt * 128) * HDIM];

    float acc[8][8];
#pragma unroll
    for (int i = 0; i < 8; i++)
#pragma unroll
        for (int j = 0; j < 8; j++) acc[i][j] = 0.0f;

    int lr = tid >> 1;
    int lc = (tid & 1) * 16;

    float4 q0[4], k0v[4];
#pragma unroll
    for (int t = 0; t < 4; t++) {
        q0[t] = *(const float4*)&Qg[(size_t)lr * HDIM + lc + t * 4];
        k0v[t] = *(const float4*)&Kg[(size_t)lr * HDIM + lc + t * 4];
    }
#pragma unroll
    for (int t = 0; t < 4; t++) {
        Qs[lc + t * 4 + 0][lr] = q0[t].x; Qs[lc + t * 4 + 1][lr] = q0[t].y;
        Qs[lc + t * 4 + 2][lr] = q0[t].z; Qs[lc + t * 4 + 3][lr] = q0[t].w;
        Ks[lc + t * 4 + 0][lr] = k0v[t].x; Ks[lc + t * 4 + 1][lr] = k0v[t].y;
        Ks[lc + t * 4 + 2][lr] = k0v[t].z; Ks[lc + t * 4 + 3][lr] = k0v[t].w;
    }
    __syncthreads();

    // prefetch slab 1 (d = 32..63)
#pragma unroll
    for (int t = 0; t < 4; t++) {
        q0[t] = *(const float4*)&Qg[(size_t)lr * HDIM + 32 + lc + t * 4];
        k0v[t] = *(const float4*)&Kg[(size_t)lr * HDIM + 32 + lc + t * 4];
    }
#pragma unroll
    for (int kk = 0; kk < 32; kk++) {
        float a[8], b[8];
        *(float4*)&a[0] = *(const float4*)&Qs[kk][ty * 8 + 0];
        *(float4*)&a[4] = *(const float4*)&Qs[kk][ty * 8 + 4];
        *(float4*)&b[0] = *(const float4*)&Ks[kk][tx * 8 + 0];
        *(float4*)&b[4] = *(const float4*)&Ks[kk][tx * 8 + 4];
#pragma unroll
        for (int i = 0; i < 8; i++)
#pragma unroll
            for (int j = 0; j < 8; j++) acc[i][j] = fmaf(a[i], b[j], acc[i][j]);
    }
    __syncthreads();
#pragma unroll
    for (int t = 0; t < 4; t++) {
        Qs[lc + t * 4 + 0][lr] = q0[t].x; Qs[lc + t * 4 + 1][lr] = q0[t].y;
        Qs[lc + t * 4 + 2][lr] = q0[t].z; Qs[lc + t * 4 + 3][lr] = q0[t].w;
        Ks[lc + t * 4 + 0][lr] = k0v[t].x; Ks[lc + t * 4 + 1][lr] = k0v[t].y;
        Ks[lc + t * 4 + 2][lr] = k0v[t].z; Ks[lc + t * 4 + 3][lr] = k0v[t].w;
    }
    __syncthreads();
#pragma unroll
    for (int kk = 0; kk < 32; kk++) {
        float a[8], b[8];
        *(float4*)&a[0] = *(const float4*)&Qs[kk][ty * 8 + 0];
        *(float4*)&a[4] = *(const float4*)&Qs[kk][ty * 8 + 4];
        *(float4*)&b[0] = *(const float4*)&Ks[kk][tx * 8 + 0];
        *(float4*)&b[4] = *(const float4*)&Ks[kk][tx * 8 + 4];
#pragma unroll
        for (int i = 0; i < 8; i++)
#pragma unroll
            for (int j = 0; j < 8; j++) acc[i][j] = fmaf(a[i], b[j], acc[i][j]);
    }

    const float scale = 0.125f;
    bool diag = (kt == qt);
#pragma unroll
    for (int i = 0; i < 8; i++) {
        int q = qt * 128 + ty * 8 + i;
        int kbase = kt * 128 + tx * 8;
        float vv[8];
#pragma unroll
        for (int j = 0; j < 8; j++) {
            float s = acc[i][j] * scale;
            vv[j] = (diag && (kbase + j > q)) ? -INFINITY : s;
        }
        float* dst = &g_P[((size_t)bh * SEQ + q) * SEQ + kbase];
        *(float4*)&dst[0] = *(float4*)&vv[0];
        *(float4*)&dst[4] = *(float4*)&vv[4];
    }
}

// ---------------- K3: exact top-64 threshold + masked softmax ----------------
__global__ __launch_bounds__(256) void topk_softmax_kernel()
{
    int row = blockIdx.x;
    int bh = row >> 11;
    int q = row & (SEQ - 1);
    size_t base = ((size_t)bh * SEQ + q) * SEQ;
    int L = q + 1;
    int tid = threadIdx.x;
    int lane = tid & 31;
    int warp = tid >> 5;

    __shared__ float sc[SEQ];
    __shared__ unsigned hist[8][256];
    __shared__ unsigned sufS[256];
    __shared__ unsigned cntS[256];
    __shared__ unsigned warpTot[8];
    __shared__ unsigned ballots[8];
    __shared__ unsigned s_prefix;
    __shared__ int s_kk;
    __shared__ float red[8];
    __shared__ float s_bval;

    for (int i = tid; i < L; i += 256) sc[i] = g_P[base + i];
    if (tid == 0) s_kk = TOPK;
    __syncthreads();

    float thresh = -INFINITY;
    if (L > TOPK) {
        unsigned prefix = 0, himask = 0;
        int kk = TOPK;
        for (int p = 24; p >= 0; p -= 8) {
            for (int i = tid; i < 8 * 256; i += 256) ((unsigned*)hist)[i] = 0;
            __syncthreads();
            for (int i = tid; i < L; i += 256) {
                unsigned u = __float_as_uint(sc[i]);
                unsigned key = (u & 0x80000000u) ? ~u : (u | 0x80000000u);
                if ((key & himask) == prefix)
                    atomicAdd(&hist[warp][(key >> p) & 0xFFu], 1u);
            }
            __syncthreads();
            unsigned cnt = 0;
#pragma unroll
            for (int w = 0; w < 8; w++) cnt += hist[w][tid];
            unsigned s = cnt;
#pragma unroll
            for (int off = 1; off < 32; off <<= 1) {
                unsigned t = __shfl_down_sync(0xFFFFFFFFu, s, off);
                if (lane + off < 32) s += t;
            }
            if (lane == 0) warpTot[warp] = s;
            __syncthreads();
            unsigned hi = 0;
            for (int w2 = warp + 1; w2 < 8; w2++) hi += warpTot[w2];
            unsigned S = s + hi;
            sufS[tid] = S;
            cntS[tid] = cnt;
            unsigned bal = __ballot_sync(0xFFFFFFFFu, S >= (unsigned)kk);
            if (lane == 0) ballots[warp] = bal;
            __syncthreads();
            if (tid == 0) {
                int sel = 0;
                for (int w = 7; w >= 0; w--) {
                    if (ballots[w]) { sel = w * 32 + (31 - __clz(ballots[w])); break; }
                }
                s_kk = s_kk - (int)(sufS[sel] - cntS[sel]);
                s_prefix = prefix | ((unsigned)sel << p);
            }
            __syncthreads();
            prefix = s_prefix;
            kk = s_kk;
            himask |= (0xFFu << p);
            __syncthreads();
        }
        unsigned key = prefix;
        unsigned u = (key & 0x80000000u) ? (key & 0x7FFFFFFFu) : ~key;
        thresh = __uint_as_float(u);
    }

    float m = -INFINITY;
    for (int i = tid; i < L; i += 256) m = fmaxf(m, sc[i]);
#pragma unroll
    for (int off = 16; off; off >>= 1) m = fmaxf(m, __shfl_xor_sync(0xFFFFFFFFu, m, off));
    if (lane == 0) red[warp] = m;
    __syncthreads();
    if (tid == 0) {
        float mm = red[0];
#pragma unroll
        for (int w = 1; w < 8; w++) mm = fmaxf(mm, red[w]);
        s_bval = mm;
    }
    __syncthreads();
    m = s_bval;

    float sum = 0.0f;
    for (int i = tid; i < L; i += 256) {
        float v = sc[i];
        float e = (v >= thresh) ? __expf(v - m) : 0.0f;
        sc[i] = e;
        sum += e;
    }
#pragma unroll
    for (int off = 16; off; off >>= 1) sum += __shfl_xor_sync(0xFFFFFFFFu, sum, off);
    if (lane == 0) red[warp] = sum;
    __syncthreads();
    if (tid == 0) {
        float ss = 0.0f;
#pragma unroll
        for (int w = 0; w < 8; w++) ss += red[w];
        s_bval = ss;
    }
    __syncthreads();
    float inv = 1.0f / s_bval;

    for (int i = tid; i < L; i += 256) g_P[base + i] = sc[i] * inv;
    int tileEnd = ((q >> 7) + 1) << 7;
    for (int i = L + tid; i < tileEnd; i += 256) g_P[base + i] = 0.0f;
}

// ---------------- K4: O = P @ V  split-bf16 tensor cores ---------------------
__global__ __launch_bounds__(256) void av_bf16_kernel()
{
    int qt = blockIdx.x;
    int bh = blockIdx.y;

    __shared__ __nv_bfloat16 Phi[128][40], Plo[128][40];
    __shared__ __nv_bfloat16 Vhi[32][72], Vlo[32][72];

    int tid = threadIdx.x;
    int lane = tid & 31;
    int wid = tid >> 5;
    int wm = wid & 3;      // 4 warp rows (32 q each)
    int wn = wid >> 2;     // 2 warp cols (32 d each)

    float acc[2][4][4];
#pragma unroll
    for (int mi = 0; mi < 2; mi++)
#pragma unroll
        for (int ni = 0; ni < 4; ni++)
#pragma unroll
            for (int r = 0; r < 4; r++) acc[mi][ni][r] = 0.0f;

    int nk = (qt + 1) * 128;
    int pr = tid >> 1, pc = (tid & 1) * 16;
    int vr = tid >> 3, vc = (tid & 7) * 8;
    const float* Pbase = &g_P[((size_t)bh * SEQ + qt * 128 + pr) * SEQ + pc];

    for (int kb = 0; kb < nk; kb += 32) {
#pragma unroll
        for (int t = 0; t < 4; t++) {
            float4 p = *(const float4*)&Pbase[kb + t * 4];
            __nv_bfloat16 h0, l0, h1, l1;
            split_bf16(p.x, h0, l0); split_bf16(p.y, h1, l1);
            *(__nv_bfloat162*)&Phi[pr][pc + t * 4] = __nv_bfloat162(h0, h1);
            *(__nv_bfloat162*)&Plo[pr][pc + t * 4] = __nv_bfloat162(l0, l1);
            split_bf16(p.z, h0, l0); split_bf16(p.w, h1, l1);
            *(__nv_bfloat162*)&Phi[pr][pc + t * 4 + 2] = __nv_bfloat162(h0, h1);
            *(__nv_bfloat162*)&Plo[pr][pc + t * 4 + 2] = __nv_bfloat162(l0, l1);
        }
        const float* Vg = &g_V[((size_t)bh * SEQ + kb + vr) * HDIM + vc];
#pragma unroll
        for (int t = 0; t < 2; t++) {
            float4 v = *(const float4*)&Vg[t * 4];
            __nv_bfloat16 h0, l0, h1, l1;
            split_bf16(v.x, h0, l0); split_bf16(v.y, h1, l1);
            *(__nv_bfloat162*)&Vhi[vr][vc + t * 4] = __nv_bfloat162(h0, h1);
            *(__nv_bfloat162*)&Vlo[vr][vc + t * 4] = __nv_bfloat162(l0, l1);
            split_bf16(v.z, h0, l0); split_bf16(v.w, h1, l1);
            *(__nv_bfloat162*)&Vhi[vr][vc + t * 4 + 2] = __nv_bfloat162(h0, h1);
            *(__nv_bfloat162*)&Vlo[vr][vc + t * 4 + 2] = __nv_bfloat162(l0, l1);
        }
        __syncthreads();
#pragma unroll
        for (int ks = 0; ks < 2; ks++) {
            int kk = ks * 16;
            uint32_t bhr[4][2], blr[4][2];
#pragma unroll
            for (int ni = 0; ni < 4; ni++) {
                ldmB2t(smem_u32(&Vhi[kk + (lane & 15)][wn * 32 + ni * 8]), bhr[ni][0], bhr[ni][1]);
                ldmB2t(smem_u32(&Vlo[kk + (lane & 15)][wn * 32 + ni * 8]), blr[ni][0], blr[ni][1]);
            }
#pragma unroll
            for (int mi = 0; mi < 2; mi++) {
                int arow = wm * 32 + mi * 16 + (lane & 15);
                int acol = kk + ((lane >> 4) << 3);
                uint32_t ah0, ah1, ah2, ah3, al0, al1, al2, al3;
                ldmA4(smem_u32(&Phi[arow][acol]), ah0, ah1, ah2, ah3);
                ldmA4(smem_u32(&Plo[arow][acol]), al0, al1, al2, al3);
#pragma unroll
                for (int ni = 0; ni < 4; ni++) {
                    mma16816(acc[mi][ni], ah0, ah1, ah2, ah3, bhr[ni][0], bhr[ni][1]);
                    mma16816(acc[mi][ni], al0, al1, al2, al3, bhr[ni][0], bhr[ni][1]);
                    mma16816(acc[mi][ni], ah0, ah1, ah2, ah3, blr[ni][0], blr[ni][1]);
                }
            }
        }
        __syncthreads();
    }

    int b = bh / NHEADS;
    int h = bh - b * NHEADS;
#pragma unroll
    for (int mi = 0; mi < 2; mi++) {
#pragma unroll
        for (int ni = 0; ni < 4; ni++) {
            int q0 = qt * 128 + wm * 32 + mi * 16 + (lane >> 2);
            int d0 = wn * 32 + ni * 8 + (lane & 3) * 2;
#pragma unroll
            for (int half = 0; half < 2; half++) {
                int q = q0 + half * 8;
                float2* dst = (float2*)&g_O[(size_t)(b * SEQ + q) * DMODEL + h * HDIM + d0];
                *dst = make_float2(acc[mi][ni][half * 2 + 0], acc[mi][ni][half * 2 + 1]);
            }
        }
    }
}

// ---------------- launch ------------------------------------------------------
extern "C" void kernel_launch(void* const* d_in, const int* in_sizes, int n_in,
                              void* d_out, int out_size)
{
    const float* h_ssm = (const float*)d_in[0];
    const float* gate  = (const float*)d_in[1];
    const float* Wq = (const float*)d_in[2];
    const float* bq = (const float*)d_in[3];
    const float* Wk = (const float*)d_in[4];
    const float* bk = (const float*)d_in[5];
    const float* Wv = (const float*)d_in[6];
    const float* bv = (const float*)d_in[7];
    const float* Wo = (const float*)d_in[8];
    const float* bo = (const float*)d_in[9];
    float* out = (float*)d_out;

    dim3 gProj(DMODEL / 128, NROWS / 128);          // (8, 32)
    gemm_kernel<<<gProj, 256>>>(h_ssm, Wq, bq, 0);
    gemm_kernel<<<gProj, 256>>>(h_ssm, Wk, bk, 1);
    gemm_bf16_kernel<<<gProj, 256>>>(h_ssm, Wv, bv, nullptr, nullptr, 2);

    scores_kernel<<<dim3(SEQ / 128, SEQ / 128, BH), 256>>>();
    topk_softmax_kernel<<<dim3(BH * SEQ), 256>>>();
    av_bf16_kernel<<<dim3(SEQ / 128, BH), 256>>>();

    gemm_bf16_kernel<<<gProj, 256>>>(nullptr, Wo, bo, out, gate, 3);
}

// round 6
// speedup vs baseline: 1.6888x; 1.0511x over previous
#include <cuda_runtime.h>
#include <cuda_bf16.h>
#include <math.h>
#include <stdint.h>

// Problem constants
#define BATCH 2
#define SEQ 2048
#define DMODEL 1024
#define NHEADS 16
#define HDIM 64
#define TOPK 64
#define NROWS (BATCH * SEQ)          // 4096
#define BH (BATCH * NHEADS)          // 32

// ---------------- scratch (device globals; allocation-free rule) -------------
__device__ float g_Q[(size_t)BH * SEQ * HDIM];   // [bh, s, d] 16MB
__device__ float g_K[(size_t)BH * SEQ * HDIM];   // 16MB
__device__ float g_V[(size_t)BH * SEQ * HDIM];   // 16MB
__device__ float g_P[(size_t)BH * SEQ * SEQ];    // scores -> probs, 512MB
__device__ float g_O[(size_t)NROWS * DMODEL];    // attn output pre-Wo, 16MB

// ---------------- f32x2 packed-fma helpers (Blackwell dual-rate fp32) --------
typedef unsigned long long u64t;
__device__ __forceinline__ u64t dup2(float x) {
    u64t d;
    unsigned u = __float_as_uint(x);
    asm("mov.b64 %0, {%1, %1};" : "=l"(d) : "r"(u));
    return d;
}
__device__ __forceinline__ void ffma2(u64t& c, u64t a, u64t b) {
    asm("fma.rn.f32x2 %0, %1, %2, %0;" : "+l"(c) : "l"(a), "l"(b));
}
__device__ __forceinline__ void unpack2(u64t d, float& x, float& y) {
    unsigned lo, hi;
    asm("mov.b64 {%0, %1}, %2;" : "=r"(lo), "=r"(hi) : "l"(d));
    x = __uint_as_float(lo);
    y = __uint_as_float(hi);
}

// ---------------- tensor-core helpers ----------------------------------------
__device__ __forceinline__ uint32_t smem_u32(const void* p) {
    return (uint32_t)__cvta_generic_to_shared(p);
}
__device__ __forceinline__ void ldmA4(uint32_t addr, uint32_t& r0, uint32_t& r1,
                                      uint32_t& r2, uint32_t& r3) {
    asm volatile("ldmatrix.sync.aligned.m8n8.x4.shared.b16 {%0,%1,%2,%3}, [%4];"
                 : "=r"(r0), "=r"(r1), "=r"(r2), "=r"(r3) : "r"(addr));
}
__device__ __forceinline__ void ldmB2t(uint32_t addr, uint32_t& r0, uint32_t& r1) {
    asm volatile("ldmatrix.sync.aligned.m8n8.x2.trans.shared.b16 {%0,%1}, [%2];"
                 : "=r"(r0), "=r"(r1) : "r"(addr));
}
__device__ __forceinline__ void mma16816(float* c, uint32_t a0, uint32_t a1,
                                         uint32_t a2, uint32_t a3,
                                         uint32_t b0, uint32_t b1) {
    asm volatile(
        "mma.sync.aligned.m16n8k16.row.col.f32.bf16.bf16.f32 "
        "{%0,%1,%2,%3}, {%4,%5,%6,%7}, {%8,%9}, {%0,%1,%2,%3};"
        : "+f"(c[0]), "+f"(c[1]), "+f"(c[2]), "+f"(c[3])
        : "r"(a0), "r"(a1), "r"(a2), "r"(a3), "r"(b0), "r"(b1));
}
__device__ __forceinline__ void split_bf16(float x, __nv_bfloat16& hi, __nv_bfloat16& lo) {
    hi = __float2bfloat16(x);
    lo = __float2bfloat16(x - __bfloat162float(hi));
}

// ---------------- K1: 128x128x16 SGEMM w/ f32x2 (Q/K projections) ------------
__global__ __launch_bounds__(256) void gemm_kernel(
    const float* __restrict__ A,
    const float* __restrict__ W,
    const float* __restrict__ bias,
    int mode)   // 0 -> g_Q, 1 -> g_K
{
    __shared__ float As[16][132];
    __shared__ float Bs[16][128];

    const int K = DMODEL;
    const int NC = DMODEL;
    int tid = threadIdx.x;
    int tx = tid & 15;
    int ty = tid >> 4;
    int rowTile = blockIdx.y * 128;
    int colTile = blockIdx.x * 128;

    float* Op = (mode == 0) ? g_Q : g_K;

    int ar = tid >> 1;
    int ac8 = (tid & 1) * 8;
    int br = tid >> 4;
    int bc8 = (tid & 15) * 8;

    // acc2[p][j] packs rows (ty*8+2p, ty*8+2p+1) at col tx*8+j
    u64t acc2[4][8];
#pragma unroll
    for (int p = 0; p < 4; p++)
#pragma unroll
        for (int j = 0; j < 8; j++) acc2[p][j] = 0ull;

    const float* aptr = &A[(size_t)(rowTile + ar) * K];
    const float* bptr = &W[(size_t)colTile + bc8];

    {
        float4 a0 = *(const float4*)&aptr[ac8 + 0];
        float4 a1 = *(const float4*)&aptr[ac8 + 4];
        As[ac8 + 0][ar] = a0.x; As[ac8 + 1][ar] = a0.y;
        As[ac8 + 2][ar] = a0.z; As[ac8 + 3][ar] = a0.w;
        As[ac8 + 4][ar] = a1.x; As[ac8 + 5][ar] = a1.y;
        As[ac8 + 6][ar] = a1.z; As[ac8 + 7][ar] = a1.w;
        *(float4*)&Bs[br][bc8 + 0] = *(const float4*)&bptr[(size_t)br * NC + 0];
        *(float4*)&Bs[br][bc8 + 4] = *(const float4*)&bptr[(size_t)br * NC + 4];
    }
    __syncthreads();

    for (int k0 = 0; k0 < K; k0 += 16) {
        bool has = (k0 + 16) < K;
        float4 pa0, pa1, pb0, pb1;
        if (has) {
            pa0 = *(const float4*)&aptr[k0 + 16 + ac8 + 0];
            pa1 = *(const float4*)&aptr[k0 + 16 + ac8 + 4];
            pb0 = *(const float4*)&bptr[(size_t)(k0 + 16 + br) * NC + 0];
            pb1 = *(const float4*)&bptr[(size_t)(k0 + 16 + br) * NC + 4];
        }
#pragma unroll
        for (int kk = 0; kk < 16; kk++) {
            u64t a2[4];
#pragma unroll
            for (int p = 0; p < 4; p++)
                a2[p] = *(const u64t*)&As[kk][ty * 8 + 2 * p];
            float b[8];
            *(float4*)&b[0] = *(const float4*)&Bs[kk][tx * 8 + 0];
            *(float4*)&b[4] = *(const float4*)&Bs[kk][tx * 8 + 4];
            u64t bb[8];
#pragma unroll
            for (int j = 0; j < 8; j++) bb[j] = dup2(b[j]);
#pragma unroll
            for (int p = 0; p < 4; p++)
#pragma unroll
                for (int j = 0; j < 8; j++) ffma2(acc2[p][j], a2[p], bb[j]);
        }
        __syncthreads();
        if (has) {
            As[ac8 + 0][ar] = pa0.x; As[ac8 + 1][ar] = pa0.y;
            As[ac8 + 2][ar] = pa0.z; As[ac8 + 3][ar] = pa0.w;
            As[ac8 + 4][ar] = pa1.x; As[ac8 + 5][ar] = pa1.y;
            As[ac8 + 6][ar] = pa1.z; As[ac8 + 7][ar] = pa1.w;
            *(float4*)&Bs[br][bc8 + 0] = pb0;
            *(float4*)&Bs[br][bc8 + 4] = pb1;
            __syncthreads();
        }
    }

#pragma unroll
    for (int p = 0; p < 4; p++) {
        float r0[8], r1[8];
#pragma unroll
        for (int j = 0; j < 8; j++) unpack2(acc2[p][j], r0[j], r1[j]);
#pragma unroll
        for (int half = 0; half < 2; half++) {
            int m = rowTile + ty * 8 + 2 * p + half;
            int b = m / SEQ;
            int s = m - b * SEQ;
            const float* rr = half ? r1 : r0;
#pragma unroll
            for (int j = 0; j < 8; j++) {
                int n = colTile + tx * 8 + j;
                int h = n >> 6;
                int d = n & 63;
                Op[((size_t)(b * NHEADS + h) * SEQ + s) * HDIM + d] = rr[j] + bias[n];
            }
        }
    }
}

// ---------------- K1b: 128x128 split-bf16 tensor-core GEMM -------------------
// mode 2: g_V = h_ssm @ Wv + bv   ([b,h,s,d] layout)
// mode 3: out = (g_O @ Wo + bo) * gate
__global__ __launch_bounds__(256) void gemm_bf16_kernel(
    const float* __restrict__ A,
    const float* __restrict__ W,
    const float* __restrict__ bias,
    float* __restrict__ outp,
    const float* __restrict__ gate,
    int mode)
{
    __shared__ __nv_bfloat16 Ahi[128][40], Alo[128][40];
    __shared__ __nv_bfloat16 Bhi[32][136], Blo[32][136];

    const int K = DMODEL;
    const int NC = DMODEL;
    int tid = threadIdx.x;
    int lane = tid & 31;
    int wid = tid >> 5;
    int wm = wid & 1;            // 2 warp rows (64 rows each)
    int wn = wid >> 1;           // 4 warp cols (32 cols each)
    int rowTile = blockIdx.y * 128;
    int colTile = blockIdx.x * 128;

    const float* Ap = (mode == 3) ? g_O : A;

    int ar = tid >> 1, ac = (tid & 1) * 16;
    int br = tid >> 3, bc = (tid & 7) * 16;
    const float* aptr = &Ap[(size_t)(rowTile + ar) * K + ac];
    const float* bptr = &W[(size_t)br * NC + colTile + bc];

    float acc[4][4][4];
#pragma unroll
    for (int mi = 0; mi < 4; mi++)
#pragma unroll
        for (int ni = 0; ni < 4; ni++)
#pragma unroll
            for (int r = 0; r < 4; r++) acc[mi][ni][r] = 0.0f;

    float4 pa[4], pb[4];
#pragma unroll
    for (int t = 0; t < 4; t++) {
        pa[t] = *(const float4*)&aptr[t * 4];
        pb[t] = *(const float4*)&bptr[t * 4];
    }
#pragma unroll
    for (int t = 0; t < 4; t++) {
        float v[4] = {pa[t].x, pa[t].y, pa[t].z, pa[t].w};
        __nv_bfloat16 h0, l0, h1, l1;
        split_bf16(v[0], h0, l0); split_bf16(v[1], h1, l1);
        *(__nv_bfloat162*)&Ahi[ar][ac + t * 4] = __nv_bfloat162(h0, h1);
        *(__nv_bfloat162*)&Alo[ar][ac + t * 4] = __nv_bfloat162(l0, l1);
        split_bf16(v[2], h0, l0); split_bf16(v[3], h1, l1);
        *(__nv_bfloat162*)&Ahi[ar][ac + t * 4 + 2] = __nv_bfloat162(h0, h1);
        *(__nv_bfloat162*)&Alo[ar][ac + t * 4 + 2] = __nv_bfloat162(l0, l1);
        float w[4] = {pb[t].x, pb[t].y, pb[t].z, pb[t].w};
        split_bf16(w[0], h0, l0); split_bf16(w[1], h1, l1);
        *(__nv_bfloat162*)&Bhi[br][bc + t * 4] = __nv_bfloat162(h0, h1);
        *(__nv_bfloat162*)&Blo[br][bc + t * 4] = __nv_bfloat162(l0, l1);
        split_bf16(w[2], h0, l0); split_bf16(w[3], h1, l1);
        *(__nv_bfloat162*)&Bhi[br][bc + t * 4 + 2] = __nv_bfloat162(h0, h1);
        *(__nv_bfloat162*)&Blo[br][bc + t * 4 + 2] = __nv_bfloat162(l0, l1);
    }
    __syncthreads();

    for (int s = 0; s < K / 32; s++) {
        bool has = (s + 1) < K / 32;
        if (has) {
            int k0 = (s + 1) * 32;
#pragma unroll
            for (int t = 0; t < 4; t++) {
                pa[t] = *(const float4*)&aptr[k0 + t * 4];
                pb[t] = *(const float4*)&bptr[(size_t)k0 * NC + t * 4];
            }
        }
#pragma unroll
        for (int ks = 0; ks < 2; ks++) {
            int kk = ks * 16;
            uint32_t bhr[4][2], blr[4][2];
#pragma unroll
            for (int ni = 0; ni < 4; ni++) {
                ldmB2t(smem_u32(&Bhi[kk + (lane & 15)][wn * 32 + ni * 8]), bhr[ni][0], bhr[ni][1]);
                ldmB2t(smem_u32(&Blo[kk + (lane & 15)][wn * 32 + ni * 8]), blr[ni][0], blr[ni][1]);
            }
#pragma unroll
            for (int mi = 0; mi < 4; mi++) {
                int arow = wm * 64 + mi * 16 + (lane & 15);
                int acol = kk + ((lane >> 4) << 3);
                uint32_t ah0, ah1, ah2, ah3, al0, al1, al2, al3;
                ldmA4(smem_u32(&Ahi[arow][acol]), ah0, ah1, ah2, ah3);
                ldmA4(smem_u32(&Alo[arow][acol]), al0, al1, al2, al3);
#pragma unroll
                for (int ni = 0; ni < 4; ni++) {
                    mma16816(acc[mi][ni], ah0, ah1, ah2, ah3, bhr[ni][0], bhr[ni][1]);
                    mma16816(acc[mi][ni], al0, al1, al2, al3, bhr[ni][0], bhr[ni][1]);
                    mma16816(acc[mi][ni], ah0, ah1, ah2, ah3, blr[ni][0], blr[ni][1]);
                }
            }
        }
        __syncthreads();
        if (has) {
#pragma unroll
            for (int t = 0; t < 4; t++) {
                float v[4] = {pa[t].x, pa[t].y, pa[t].z, pa[t].w};
                __nv_bfloat16 h0, l0, h1, l1;
                split_bf16(v[0], h0, l0); split_bf16(v[1], h1, l1);
                *(__nv_bfloat162*)&Ahi[ar][ac + t * 4] = __nv_bfloat162(h0, h1);
                *(__nv_bfloat162*)&Alo[ar][ac + t * 4] = __nv_bfloat162(l0, l1);
                split_bf16(v[2], h0, l0); split_bf16(v[3], h1, l1);
                *(__nv_bfloat162*)&Ahi[ar][ac + t * 4 + 2] = __nv_bfloat162(h0, h1);
                *(__nv_bfloat162*)&Alo[ar][ac + t * 4 + 2] = __nv_bfloat162(l0, l1);
                float w[4] = {pb[t].x, pb[t].y, pb[t].z, pb[t].w};
                split_bf16(w[0], h0, l0); split_bf16(w[1], h1, l1);
                *(__nv_bfloat162*)&Bhi[br][bc + t * 4] = __nv_bfloat162(h0, h1);
                *(__nv_bfloat162*)&Blo[br][bc + t * 4] = __nv_bfloat162(l0, l1);
                split_bf16(w[2], h0, l0); split_bf16(w[3], h1, l1);
                *(__nv_bfloat162*)&Bhi[br][bc + t * 4 + 2] = __nv_bfloat162(h0, h1);
                *(__nv_bfloat162*)&Blo[br][bc + t * 4 + 2] = __nv_bfloat162(l0, l1);
            }
            __syncthreads();
        }
    }

#pragma unroll
    for (int mi = 0; mi < 4; mi++) {
#pragma unroll
        for (int ni = 0; ni < 4; ni++) {
            int row0 = rowTile + wm * 64 + mi * 16 + (lane >> 2);
            int col0 = colTile + wn * 32 + ni * 8 + (lane & 3) * 2;
            float b0 = bias[col0], b1 = bias[col0 + 1];
#pragma unroll
            for (int half = 0; half < 2; half++) {
                int m = row0 + half * 8;
                float v0 = acc[mi][ni][half * 2 + 0] + b0;
                float v1 = acc[mi][ni][half * 2 + 1] + b1;
                if (mode == 2) {
                    int b = m / SEQ;
                    int ss = m - b * SEQ;
                    int h = col0 >> 6;
                    int d = col0 & 63;
                    float2* dst = (float2*)&g_V[((size_t)(b * NHEADS + h) * SEQ + ss) * HDIM + d];
                    *dst = make_float2(v0, v1);
                } else {
                    float gm = gate[m];
                    float2* dst = (float2*)&outp[(size_t)m * DMODEL + col0];
                    *dst = make_float2(v0 * gm, v1 * gm);
                }
            }
        }
    }
}

// ---------------- K2: scores = Q K^T / 8, causal, 128x128, f32x2 -------------
__global__ __launch_bounds__(256) void scores_kernel()
{
    int kt = blockIdx.x;
    int qt = blockIdx.y;
    int bh = blockIdx.z;
    if (kt > qt) return;

    __shared__ float Qs[32][132];
    __shared__ float Ks[32][132];

    int tid = threadIdx.x;
    int tx = tid & 15;
    int ty = tid >> 4;
    const float* Qg = &g_Q[((size_t)bh * SEQ + qt * 128) * HDIM];
    const float* Kg = &g_K[((size_t)bh * SEQ + kt * 128) * HDIM];

    // acc2[p][j] packs q-rows (ty*8+2p, +1) at k-col tx*8+j
    u64t acc2[4][8];
#pragma unroll
    for (int p = 0; p < 4; p++)
#pragma unroll
        for (int j = 0; j < 8; j++) acc2[p][j] = 0ull;

    int lr = tid >> 1;
    int lc = (tid & 1) * 16;

    for (int d0 = 0; d0 < HDIM; d0 += 32) {
#pragma unroll
        for (int t = 0; t < 4; t++) {
            float4 qv = *(const float4*)&Qg[(size_t)lr * HDIM + d0 + lc + t * 4];
            Qs[lc + t * 4 + 0][lr] = qv.x; Qs[lc + t * 4 + 1][lr] = qv.y;
            Qs[lc + t * 4 + 2][lr] = qv.z; Qs[lc + t * 4 + 3][lr] = qv.w;
            float4 kv = *(const float4*)&Kg[(size_t)lr * HDIM + d0 + lc + t * 4];
            Ks[lc + t * 4 + 0][lr] = kv.x; Ks[lc + t * 4 + 1][lr] = kv.y;
            Ks[lc + t * 4 + 2][lr] = kv.z; Ks[lc + t * 4 + 3][lr] = kv.w;
        }
        __syncthreads();
#pragma unroll
        for (int kk = 0; kk < 32; kk++) {
            u64t a2[4];
#pragma unroll
            for (int p = 0; p < 4; p++)
                a2[p] = *(const u64t*)&Qs[kk][ty * 8 + 2 * p];
            float b[8];
            *(float4*)&b[0] = *(const float4*)&Ks[kk][tx * 8 + 0];
            *(float4*)&b[4] = *(const float4*)&Ks[kk][tx * 8 + 4];
            u64t bb[8];
#pragma unroll
            for (int j = 0; j < 8; j++) bb[j] = dup2(b[j]);
#pragma unroll
            for (int p = 0; p < 4; p++)
#pragma unroll
                for (int j = 0; j < 8; j++) ffma2(acc2[p][j], a2[p], bb[j]);
        }
        __syncthreads();
    }

    const float scale = 0.125f;
    bool diag = (kt == qt);
#pragma unroll
    for (int p = 0; p < 4; p++) {
        float r0[8], r1[8];
#pragma unroll
        for (int j = 0; j < 8; j++) unpack2(acc2[p][j], r0[j], r1[j]);
#pragma unroll
        for (int half = 0; half < 2; half++) {
            int q = qt * 128 + ty * 8 + 2 * p + half;
            int kbase = kt * 128 + tx * 8;
            const float* rr = half ? r1 : r0;
            float vv[8];
#pragma unroll
            for (int j = 0; j < 8; j++) {
                float s = rr[j] * scale;
                vv[j] = (diag && (kbase + j > q)) ? -INFINITY : s;
            }
            float* dst = &g_P[((size_t)bh * SEQ + q) * SEQ + kbase];
            *(float4*)&dst[0] = *(float4*)&vv[0];
            *(float4*)&dst[4] = *(float4*)&vv[4];
        }
    }
}

// ---------------- K3: exact top-64 threshold + masked softmax ----------------
__global__ __launch_bounds__(256) void topk_softmax_kernel()
{
    int row = blockIdx.x;
    int bh = row >> 11;
    int q = row & (SEQ - 1);
    size_t base = ((size_t)bh * SEQ + q) * SEQ;
    int L = q + 1;
    int tid = threadIdx.x;
    int lane = tid & 31;
    int warp = tid >> 5;

    __shared__ float sc[SEQ];
    __shared__ unsigned hist[8][256];
    __shared__ unsigned sufS[256];
    __shared__ unsigned cntS[256];
    __shared__ unsigned warpTot[8];
    __shared__ unsigned ballots[8];
    __shared__ unsigned s_prefix;
    __shared__ int s_kk;
    __shared__ float red[8];
    __shared__ float s_bval;

    for (int i = tid; i < L; i += 256) sc[i] = g_P[base + i];
    if (tid == 0) s_kk = TOPK;
    __syncthreads();

    float thresh = -INFINITY;
    if (L > TOPK) {
        unsigned prefix = 0, himask = 0;
        int kk = TOPK;
        for (int p = 24; p >= 0; p -= 8) {
            for (int i = tid; i < 8 * 256; i += 256) ((unsigned*)hist)[i] = 0;
            __syncthreads();
            for (int i = tid; i < L; i += 256) {
                unsigned u = __float_as_uint(sc[i]);
                unsigned key = (u & 0x80000000u) ? ~u : (u | 0x80000000u);
                if ((key & himask) == prefix)
                    atomicAdd(&hist[warp][(key >> p) & 0xFFu], 1u);
            }
            __syncthreads();
            unsigned cnt = 0;
#pragma unroll
            for (int w = 0; w < 8; w++) cnt += hist[w][tid];
            unsigned s = cnt;
#pragma unroll
            for (int off = 1; off < 32; off <<= 1) {
                unsigned t = __shfl_down_sync(0xFFFFFFFFu, s, off);
                if (lane + off < 32) s += t;
            }
            if (lane == 0) warpTot[warp] = s;
            __syncthreads();
            unsigned hi = 0;
            for (int w2 = warp + 1; w2 < 8; w2++) hi += warpTot[w2];
            unsigned S = s + hi;
            sufS[tid] = S;
            cntS[tid] = cnt;
            unsigned bal = __ballot_sync(0xFFFFFFFFu, S >= (unsigned)kk);
            if (lane == 0) ballots[warp] = bal;
            __syncthreads();
            if (tid == 0) {
                int sel = 0;
                for (int w = 7; w >= 0; w--) {
                    if (ballots[w]) { sel = w * 32 + (31 - __clz(ballots[w])); break; }
                }
                s_kk = s_kk - (int)(sufS[sel] - cntS[sel]);
                s_prefix = prefix | ((unsigned)sel << p);
            }
            __syncthreads();
            prefix = s_prefix;
            kk = s_kk;
            himask |= (0xFFu << p);
            __syncthreads();
        }
        unsigned key = prefix;
        unsigned u = (key & 0x80000000u) ? (key & 0x7FFFFFFFu) : ~key;
        thresh = __uint_as_float(u);
    }

    float m = -INFINITY;
    for (int i = tid; i < L; i += 256) m = fmaxf(m, sc[i]);
#pragma unroll
    for (int off = 16; off; off >>= 1) m = fmaxf(m, __shfl_xor_sync(0xFFFFFFFFu, m, off));
    if (lane == 0) red[warp] = m;
    __syncthreads();
    if (tid == 0) {
        float mm = red[0];
#pragma unroll
        for (int w = 1; w < 8; w++) mm = fmaxf(mm, red[w]);
        s_bval = mm;
    }
    __syncthreads();
    m = s_bval;

    float sum = 0.0f;
    for (int i = tid; i < L; i += 256) {
        float v = sc[i];
        float e = (v >= thresh) ? __expf(v - m) : 0.0f;
        sc[i] = e;
        sum += e;
    }
#pragma unroll
    for (int off = 16; off; off >>= 1) sum += __shfl_xor_sync(0xFFFFFFFFu, sum, off);
    if (lane == 0) red[warp] = sum;
    __syncthreads();
    if (tid == 0) {
        float ss = 0.0f;
#pragma unroll
        for (int w = 0; w < 8; w++) ss += red[w];
        s_bval = ss;
    }
    __syncthreads();
    float inv = 1.0f / s_bval;

    for (int i = tid; i < L; i += 256) g_P[base + i] = sc[i] * inv;
    int tileEnd = ((q >> 7) + 1) << 7;
    for (int i = L + tid; i < tileEnd; i += 256) g_P[base + i] = 0.0f;
}

// ---------------- K4: O = P @ V  split-bf16 tensor cores ---------------------
__global__ __launch_bounds__(256) void av_bf16_kernel()
{
    int qt = blockIdx.x;
    int bh = blockIdx.y;

    __shared__ __nv_bfloat16 Phi[128][40], Plo[128][40];
    __shared__ __nv_bfloat16 Vhi[32][72], Vlo[32][72];

    int tid = threadIdx.x;
    int lane = tid & 31;
    int wid = tid >> 5;
    int wm = wid & 3;      // 4 warp rows (32 q each)
    int wn = wid >> 2;     // 2 warp cols (32 d each)

    float acc[2][4][4];
#pragma unroll
    for (int mi = 0; mi < 2; mi++)
#pragma unroll
        for (int ni = 0; ni < 4; ni++)
#pragma unroll
            for (int r = 0; r < 4; r++) acc[mi][ni][r] = 0.0f;

    int nk = (qt + 1) * 128;
    int pr = tid >> 1, pc = (tid & 1) * 16;
    int vr = tid >> 3, vc = (tid & 7) * 8;
    const float* Pbase = &g_P[((size_t)bh * SEQ + qt * 128 + pr) * SEQ + pc];

    for (int kb = 0; kb < nk; kb += 32) {
#pragma unroll
        for (int t = 0; t < 4; t++) {
            float4 p = *(const float4*)&Pbase[kb + t * 4];
            __nv_bfloat16 h0, l0, h1, l1;
            split_bf16(p.x, h0, l0); split_bf16(p.y, h1, l1);
            *(__nv_bfloat162*)&Phi[pr][pc + t * 4] = __nv_bfloat162(h0, h1);
            *(__nv_bfloat162*)&Plo[pr][pc + t * 4] = __nv_bfloat162(l0, l1);
            split_bf16(p.z, h0, l0); split_bf16(p.w, h1, l1);
            *(__nv_bfloat162*)&Phi[pr][pc + t * 4 + 2] = __nv_bfloat162(h0, h1);
            *(__nv_bfloat162*)&Plo[pr][pc + t * 4 + 2] = __nv_bfloat162(l0, l1);
        }
        const float* Vg = &g_V[((size_t)bh * SEQ + kb + vr) * HDIM + vc];
#pragma unroll
        for (int t = 0; t < 2; t++) {
            float4 v = *(const float4*)&Vg[t * 4];
            __nv_bfloat16 h0, l0, h1, l1;
            split_bf16(v.x, h0, l0); split_bf16(v.y, h1, l1);
            *(__nv_bfloat162*)&Vhi[vr][vc + t * 4] = __nv_bfloat162(h0, h1);
            *(__nv_bfloat162*)&Vlo[vr][vc + t * 4] = __nv_bfloat162(l0, l1);
            split_bf16(v.z, h0, l0); split_bf16(v.w, h1, l1);
            *(__nv_bfloat162*)&Vhi[vr][vc + t * 4 + 2] = __nv_bfloat162(h0, h1);
            *(__nv_bfloat162*)&Vlo[vr][vc + t * 4 + 2] = __nv_bfloat162(l0, l1);
        }
        __syncthreads();
#pragma unroll
        for (int ks = 0; ks < 2; ks++) {
            int kk = ks * 16;
            uint32_t bhr[4][2], blr[4][2];
#pragma unroll
            for (int ni = 0; ni < 4; ni++) {
                ldmB2t(smem_u32(&Vhi[kk + (lane & 15)][wn * 32 + ni * 8]), bhr[ni][0], bhr[ni][1]);
                ldmB2t(smem_u32(&Vlo[kk + (lane & 15)][wn * 32 + ni * 8]), blr[ni][0], blr[ni][1]);
            }
#pragma unroll
            for (int mi = 0; mi < 2; mi++) {
                int arow = wm * 32 + mi * 16 + (lane & 15);
                int acol = kk + ((lane >> 4) << 3);
                uint32_t ah0, ah1, ah2, ah3, al0, al1, al2, al3;
                ldmA4(smem_u32(&Phi[arow][acol]), ah0, ah1, ah2, ah3);
                ldmA4(smem_u32(&Plo[arow][acol]), al0, al1, al2, al3);
#pragma unroll
                for (int ni = 0; ni < 4; ni++) {
                    mma16816(acc[mi][ni], ah0, ah1, ah2, ah3, bhr[ni][0], bhr[ni][1]);
                    mma16816(acc[mi][ni], al0, al1, al2, al3, bhr[ni][0], bhr[ni][1]);
                    mma16816(acc[mi][ni], ah0, ah1, ah2, ah3, blr[ni][0], blr[ni][1]);
                }
            }
        }
        __syncthreads();
    }

    int b = bh / NHEADS;
    int h = bh - b * NHEADS;
#pragma unroll
    for (int mi = 0; mi < 2; mi++) {
#pragma unroll
        for (int ni = 0; ni < 4; ni++) {
            int q0 = qt * 128 + wm * 32 + mi * 16 + (lane >> 2);
            int d0 = wn * 32 + ni * 8 + (lane & 3) * 2;
#pragma unroll
            for (int half = 0; half < 2; half++) {
                int q = q0 + half * 8;
                float2* dst = (float2*)&g_O[(size_t)(b * SEQ + q) * DMODEL + h * HDIM + d0];
                *dst = make_float2(acc[mi][ni][half * 2 + 0], acc[mi][ni][half * 2 + 1]);
            }
        }
    }
}

// ---------------- launch ------------------------------------------------------
extern "C" void kernel_launch(void* const* d_in, const int* in_sizes, int n_in,
                              void* d_out, int out_size)
{
    const float* h_ssm = (const float*)d_in[0];
    const float* gate  = (const float*)d_in[1];
    const float* Wq = (const float*)d_in[2];
    const float* bq = (const float*)d_in[3];
    const float* Wk = (const float*)d_in[4];
    const float* bk = (const float*)d_in[5];
    const float* Wv = (const float*)d_in[6];
    const float* bv = (const float*)d_in[7];
    const float* Wo = (const float*)d_in[8];
    const float* bo = (const float*)d_in[9];
    float* out = (float*)d_out;

    dim3 gProj(DMODEL / 128, NROWS / 128);          // (8, 32)
    gemm_kernel<<<gProj, 256>>>(h_ssm, Wq, bq, 0);
    gemm_kernel<<<gProj, 256>>>(h_ssm, Wk, bk, 1);
    gemm_bf16_kernel<<<gProj, 256>>>(h_ssm, Wv, bv, nullptr, nullptr, 2);

    scores_kernel<<<dim3(SEQ / 128, SEQ / 128, BH), 256>>>();
    topk_softmax_kernel<<<dim3(BH * SEQ), 256>>>();
    av_bf16_kernel<<<dim3(SEQ / 128, BH), 256>>>();

    gemm_bf16_kernel<<<gProj, 256>>>(nullptr, Wo, bo, out, gate, 3);
}

// round 7
// speedup vs baseline: 1.7035x; 1.0087x over previous
#include <cuda_runtime.h>
#include <cuda_bf16.h>
#include <math.h>
#include <stdint.h>

// Problem constants
#define BATCH 2
#define SEQ 2048
#define DMODEL 1024
#define NHEADS 16
#define HDIM 64
#define TOPK 64
#define NROWS (BATCH * SEQ)          // 4096
#define BH (BATCH * NHEADS)          // 32

// ---------------- scratch (device globals; allocation-free rule) -------------
__device__ float g_Q[(size_t)BH * SEQ * HDIM];   // [bh, s, d] 16MB
__device__ float g_K[(size_t)BH * SEQ * HDIM];   // 16MB
__device__ float g_V[(size_t)BH * SEQ * HDIM];   // 16MB
__device__ float g_P[(size_t)BH * SEQ * SEQ];    // scores -> probs, 512MB
__device__ float g_O[(size_t)NROWS * DMODEL];    // attn output pre-Wo, 16MB

// ---------------- f32x2 packed-fma helpers (Blackwell dual-rate fp32) --------
typedef unsigned long long u64t;
__device__ __forceinline__ u64t dup2(float x) {
    u64t d;
    unsigned u = __float_as_uint(x);
    asm("mov.b64 %0, {%1, %1};" : "=l"(d) : "r"(u));
    return d;
}
__device__ __forceinline__ void ffma2(u64t& c, u64t a, u64t b) {
    asm("fma.rn.f32x2 %0, %1, %2, %0;" : "+l"(c) : "l"(a), "l"(b));
}
__device__ __forceinline__ void unpack2(u64t d, float& x, float& y) {
    unsigned lo, hi;
    asm("mov.b64 {%0, %1}, %2;" : "=r"(lo), "=r"(hi) : "l"(d));
    x = __uint_as_float(lo);
    y = __uint_as_float(hi);
}

// ---------------- tensor-core helpers ----------------------------------------
__device__ __forceinline__ uint32_t smem_u32(const void* p) {
    return (uint32_t)__cvta_generic_to_shared(p);
}
__device__ __forceinline__ void ldmA4(uint32_t addr, uint32_t& r0, uint32_t& r1,
                                      uint32_t& r2, uint32_t& r3) {
    asm volatile("ldmatrix.sync.aligned.m8n8.x4.shared.b16 {%0,%1,%2,%3}, [%4];"
                 : "=r"(r0), "=r"(r1), "=r"(r2), "=r"(r3) : "r"(addr));
}
__device__ __forceinline__ void ldmB2t(uint32_t addr, uint32_t& r0, uint32_t& r1) {
    asm volatile("ldmatrix.sync.aligned.m8n8.x2.trans.shared.b16 {%0,%1}, [%2];"
                 : "=r"(r0), "=r"(r1) : "r"(addr));
}
__device__ __forceinline__ void mma16816(float* c, uint32_t a0, uint32_t a1,
                                         uint32_t a2, uint32_t a3,
                                         uint32_t b0, uint32_t b1) {
    asm volatile(
        "mma.sync.aligned.m16n8k16.row.col.f32.bf16.bf16.f32 "
        "{%0,%1,%2,%3}, {%4,%5,%6,%7}, {%8,%9}, {%0,%1,%2,%3};"
        : "+f"(c[0]), "+f"(c[1]), "+f"(c[2]), "+f"(c[3])
        : "r"(a0), "r"(a1), "r"(a2), "r"(a3), "r"(b0), "r"(b1));
}
__device__ __forceinline__ void split_bf16(float x, __nv_bfloat16& hi, __nv_bfloat16& lo) {
    hi = __float2bfloat16(x);
    lo = __float2bfloat16(x - __bfloat162float(hi));
}

// ---------------- K1: 128x128x16 SGEMM w/ f32x2 (Q/K projections) ------------
__global__ __launch_bounds__(256) void gemm_kernel(
    const float* __restrict__ A,
    const float* __restrict__ W,
    const float* __restrict__ bias,
    int mode)   // 0 -> g_Q, 1 -> g_K
{
    __shared__ float As[16][132];
    __shared__ float Bs[16][128];

    const int K = DMODEL;
    const int NC = DMODEL;
    int tid = threadIdx.x;
    int tx = tid & 15;
    int ty = tid >> 4;
    int rowTile = blockIdx.y * 128;
    int colTile = blockIdx.x * 128;

    float* Op = (mode == 0) ? g_Q : g_K;

    int ar = tid >> 1;
    int ac8 = (tid & 1) * 8;
    int br = tid >> 4;
    int bc8 = (tid & 15) * 8;

    u64t acc2[4][8];
#pragma unroll
    for (int p = 0; p < 4; p++)
#pragma unroll
        for (int j = 0; j < 8; j++) acc2[p][j] = 0ull;

    const float* aptr = &A[(size_t)(rowTile + ar) * K];
    const float* bptr = &W[(size_t)colTile + bc8];

    {
        float4 a0 = *(const float4*)&aptr[ac8 + 0];
        float4 a1 = *(const float4*)&aptr[ac8 + 4];
        As[ac8 + 0][ar] = a0.x; As[ac8 + 1][ar] = a0.y;
        As[ac8 + 2][ar] = a0.z; As[ac8 + 3][ar] = a0.w;
        As[ac8 + 4][ar] = a1.x; As[ac8 + 5][ar] = a1.y;
        As[ac8 + 6][ar] = a1.z; As[ac8 + 7][ar] = a1.w;
        *(float4*)&Bs[br][bc8 + 0] = *(const float4*)&bptr[(size_t)br * NC + 0];
        *(float4*)&Bs[br][bc8 + 4] = *(const float4*)&bptr[(size_t)br * NC + 4];
    }
    __syncthreads();

    for (int k0 = 0; k0 < K; k0 += 16) {
        bool has = (k0 + 16) < K;
        float4 pa0, pa1, pb0, pb1;
        if (has) {
            pa0 = *(const float4*)&aptr[k0 + 16 + ac8 + 0];
            pa1 = *(const float4*)&aptr[k0 + 16 + ac8 + 4];
            pb0 = *(const float4*)&bptr[(size_t)(k0 + 16 + br) * NC + 0];
            pb1 = *(const float4*)&bptr[(size_t)(k0 + 16 + br) * NC + 4];
        }
#pragma unroll
        for (int kk = 0; kk < 16; kk++) {
            u64t a2[4];
#pragma unroll
            for (int p = 0; p < 4; p++)
                a2[p] = *(const u64t*)&As[kk][ty * 8 + 2 * p];
            float b[8];
            *(float4*)&b[0] = *(const float4*)&Bs[kk][tx * 8 + 0];
            *(float4*)&b[4] = *(const float4*)&Bs[kk][tx * 8 + 4];
            u64t bb[8];
#pragma unroll
            for (int j = 0; j < 8; j++) bb[j] = dup2(b[j]);
#pragma unroll
            for (int p = 0; p < 4; p++)
#pragma unroll
                for (int j = 0; j < 8; j++) ffma2(acc2[p][j], a2[p], bb[j]);
        }
        __syncthreads();
        if (has) {
            As[ac8 + 0][ar] = pa0.x; As[ac8 + 1][ar] = pa0.y;
            As[ac8 + 2][ar] = pa0.z; As[ac8 + 3][ar] = pa0.w;
            As[ac8 + 4][ar] = pa1.x; As[ac8 + 5][ar] = pa1.y;
            As[ac8 + 6][ar] = pa1.z; As[ac8 + 7][ar] = pa1.w;
            *(float4*)&Bs[br][bc8 + 0] = pb0;
            *(float4*)&Bs[br][bc8 + 4] = pb1;
            __syncthreads();
        }
    }

#pragma unroll
    for (int p = 0; p < 4; p++) {
        float r0[8], r1[8];
#pragma unroll
        for (int j = 0; j < 8; j++) unpack2(acc2[p][j], r0[j], r1[j]);
#pragma unroll
        for (int half = 0; half < 2; half++) {
            int m = rowTile + ty * 8 + 2 * p + half;
            int b = m / SEQ;
            int s = m - b * SEQ;
            const float* rr = half ? r1 : r0;
#pragma unroll
            for (int j = 0; j < 8; j++) {
                int n = colTile + tx * 8 + j;
                int h = n >> 6;
                int d = n & 63;
                Op[((size_t)(b * NHEADS + h) * SEQ + s) * HDIM + d] = rr[j] + bias[n];
            }
        }
    }
}

// ---------------- K1b: 128x128 split-bf16 tensor-core GEMM -------------------
__global__ __launch_bounds__(256) void gemm_bf16_kernel(
    const float* __restrict__ A,
    const float* __restrict__ W,
    const float* __restrict__ bias,
    float* __restrict__ outp,
    const float* __restrict__ gate,
    int mode)
{
    __shared__ __nv_bfloat16 Ahi[128][40], Alo[128][40];
    __shared__ __nv_bfloat16 Bhi[32][136], Blo[32][136];

    const int K = DMODEL;
    const int NC = DMODEL;
    int tid = threadIdx.x;
    int lane = tid & 31;
    int wid = tid >> 5;
    int wm = wid & 1;
    int wn = wid >> 1;
    int rowTile = blockIdx.y * 128;
    int colTile = blockIdx.x * 128;

    const float* Ap = (mode == 3) ? g_O : A;

    int ar = tid >> 1, ac = (tid & 1) * 16;
    int br = tid >> 3, bc = (tid & 7) * 16;
    const float* aptr = &Ap[(size_t)(rowTile + ar) * K + ac];
    const float* bptr = &W[(size_t)br * NC + colTile + bc];

    float acc[4][4][4];
#pragma unroll
    for (int mi = 0; mi < 4; mi++)
#pragma unroll
        for (int ni = 0; ni < 4; ni++)
#pragma unroll
            for (int r = 0; r < 4; r++) acc[mi][ni][r] = 0.0f;

    float4 pa[4], pb[4];
#pragma unroll
    for (int t = 0; t < 4; t++) {
        pa[t] = *(const float4*)&aptr[t * 4];
        pb[t] = *(const float4*)&bptr[t * 4];
    }
#pragma unroll
    for (int t = 0; t < 4; t++) {
        float v[4] = {pa[t].x, pa[t].y, pa[t].z, pa[t].w};
        __nv_bfloat16 h0, l0, h1, l1;
        split_bf16(v[0], h0, l0); split_bf16(v[1], h1, l1);
        *(__nv_bfloat162*)&Ahi[ar][ac + t * 4] = __nv_bfloat162(h0, h1);
        *(__nv_bfloat162*)&Alo[ar][ac + t * 4] = __nv_bfloat162(l0, l1);
        split_bf16(v[2], h0, l0); split_bf16(v[3], h1, l1);
        *(__nv_bfloat162*)&Ahi[ar][ac + t * 4 + 2] = __nv_bfloat162(h0, h1);
        *(__nv_bfloat162*)&Alo[ar][ac + t * 4 + 2] = __nv_bfloat162(l0, l1);
        float w[4] = {pb[t].x, pb[t].y, pb[t].z, pb[t].w};
        split_bf16(w[0], h0, l0); split_bf16(w[1], h1, l1);
        *(__nv_bfloat162*)&Bhi[br][bc + t * 4] = __nv_bfloat162(h0, h1);
        *(__nv_bfloat162*)&Blo[br][bc + t * 4] = __nv_bfloat162(l0, l1);
        split_bf16(w[2], h0, l0); split_bf16(w[3], h1, l1);
        *(__nv_bfloat162*)&Bhi[br][bc + t * 4 + 2] = __nv_bfloat162(h0, h1);
        *(__nv_bfloat162*)&Blo[br][bc + t * 4 + 2] = __nv_bfloat162(l0, l1);
    }
    __syncthreads();

    for (int s = 0; s < K / 32; s++) {
        bool has = (s + 1) < K / 32;
        if (has) {
            int k0 = (s + 1) * 32;
#pragma unroll
            for (int t = 0; t < 4; t++) {
                pa[t] = *(const float4*)&aptr[k0 + t * 4];
                pb[t] = *(const float4*)&bptr[(size_t)k0 * NC + t * 4];
            }
        }
#pragma unroll
        for (int ks = 0; ks < 2; ks++) {
            int kk = ks * 16;
            uint32_t bhr[4][2], blr[4][2];
#pragma unroll
            for (int ni = 0; ni < 4; ni++) {
                ldmB2t(smem_u32(&Bhi[kk + (lane & 15)][wn * 32 + ni * 8]), bhr[ni][0], bhr[ni][1]);
                ldmB2t(smem_u32(&Blo[kk + (lane & 15)][wn * 32 + ni * 8]), blr[ni][0], blr[ni][1]);
            }
#pragma unroll
            for (int mi = 0; mi < 4; mi++) {
                int arow = wm * 64 + mi * 16 + (lane & 15);
                int acol = kk + ((lane >> 4) << 3);
                uint32_t ah0, ah1, ah2, ah3, al0, al1, al2, al3;
                ldmA4(smem_u32(&Ahi[arow][acol]), ah0, ah1, ah2, ah3);
                ldmA4(smem_u32(&Alo[arow][acol]), al0, al1, al2, al3);
#pragma unroll
                for (int ni = 0; ni < 4; ni++) {
                    mma16816(acc[mi][ni], ah0, ah1, ah2, ah3, bhr[ni][0], bhr[ni][1]);
                    mma16816(acc[mi][ni], al0, al1, al2, al3, bhr[ni][0], bhr[ni][1]);
                    mma16816(acc[mi][ni], ah0, ah1, ah2, ah3, blr[ni][0], blr[ni][1]);
                }
            }
        }
        __syncthreads();
        if (has) {
#pragma unroll
            for (int t = 0; t < 4; t++) {
                float v[4] = {pa[t].x, pa[t].y, pa[t].z, pa[t].w};
                __nv_bfloat16 h0, l0, h1, l1;
                split_bf16(v[0], h0, l0); split_bf16(v[1], h1, l1);
                *(__nv_bfloat162*)&Ahi[ar][ac + t * 4] = __nv_bfloat162(h0, h1);
                *(__nv_bfloat162*)&Alo[ar][ac + t * 4] = __nv_bfloat162(l0, l1);
                split_bf16(v[2], h0, l0); split_bf16(v[3], h1, l1);
                *(__nv_bfloat162*)&Ahi[ar][ac + t * 4 + 2] = __nv_bfloat162(h0, h1);
                *(__nv_bfloat162*)&Alo[ar][ac + t * 4 + 2] = __nv_bfloat162(l0, l1);
                float w[4] = {pb[t].x, pb[t].y, pb[t].z, pb[t].w};
                split_bf16(w[0], h0, l0); split_bf16(w[1], h1, l1);
                *(__nv_bfloat162*)&Bhi[br][bc + t * 4] = __nv_bfloat162(h0, h1);
                *(__nv_bfloat162*)&Blo[br][bc + t * 4] = __nv_bfloat162(l0, l1);
                split_bf16(w[2], h0, l0); split_bf16(w[3], h1, l1);
                *(__nv_bfloat162*)&Bhi[br][bc + t * 4 + 2] = __nv_bfloat162(h0, h1);
                *(__nv_bfloat162*)&Blo[br][bc + t * 4 + 2] = __nv_bfloat162(l0, l1);
            }
            __syncthreads();
        }
    }

#pragma unroll
    for (int mi = 0; mi < 4; mi++) {
#pragma unroll
        for (int ni = 0; ni < 4; ni++) {
            int row0 = rowTile + wm * 64 + mi * 16 + (lane >> 2);
            int col0 = colTile + wn * 32 + ni * 8 + (lane & 3) * 2;
            float b0 = bias[col0], b1 = bias[col0 + 1];
#pragma unroll
            for (int half = 0; half < 2; half++) {
                int m = row0 + half * 8;
                float v0 = acc[mi][ni][half * 2 + 0] + b0;
                float v1 = acc[mi][ni][half * 2 + 1] + b1;
                if (mode == 2) {
                    int b = m / SEQ;
                    int ss = m - b * SEQ;
                    int h = col0 >> 6;
                    int d = col0 & 63;
                    float2* dst = (float2*)&g_V[((size_t)(b * NHEADS + h) * SEQ + ss) * HDIM + d];
                    *dst = make_float2(v0, v1);
                } else {
                    float gm = gate[m];
                    float2* dst = (float2*)&outp[(size_t)m * DMODEL + col0];
                    *dst = make_float2(v0 * gm, v1 * gm);
                }
            }
        }
    }
}

// ---------------- K2: scores = Q K^T / 8, causal, 128x128, f32x2 -------------
__global__ __launch_bounds__(256) void scores_kernel()
{
    int kt = blockIdx.x;
    int qt = blockIdx.y;
    int bh = blockIdx.z;
    if (kt > qt) return;

    __shared__ float Qs[32][132];
    __shared__ float Ks[32][132];

    int tid = threadIdx.x;
    int tx = tid & 15;
    int ty = tid >> 4;
    const float* Qg = &g_Q[((size_t)bh * SEQ + qt * 128) * HDIM];
    const float* Kg = &g_K[((size_t)bh * SEQ + kt * 128) * HDIM];

    u64t acc2[4][8];
#pragma unroll
    for (int p = 0; p < 4; p++)
#pragma unroll
        for (int j = 0; j < 8; j++) acc2[p][j] = 0ull;

    int lr = tid >> 1;
    int lc = (tid & 1) * 16;

    for (int d0 = 0; d0 < HDIM; d0 += 32) {
#pragma unroll
        for (int t = 0; t < 4; t++) {
            float4 qv = *(const float4*)&Qg[(size_t)lr * HDIM + d0 + lc + t * 4];
            Qs[lc + t * 4 + 0][lr] = qv.x; Qs[lc + t * 4 + 1][lr] = qv.y;
            Qs[lc + t * 4 + 2][lr] = qv.z; Qs[lc + t * 4 + 3][lr] = qv.w;
            float4 kv = *(const float4*)&Kg[(size_t)lr * HDIM + d0 + lc + t * 4];
            Ks[lc + t * 4 + 0][lr] = kv.x; Ks[lc + t * 4 + 1][lr] = kv.y;
            Ks[lc + t * 4 + 2][lr] = kv.z; Ks[lc + t * 4 + 3][lr] = kv.w;
        }
        __syncthreads();
#pragma unroll
        for (int kk = 0; kk < 32; kk++) {
            u64t a2[4];
#pragma unroll
            for (int p = 0; p < 4; p++)
                a2[p] = *(const u64t*)&Qs[kk][ty * 8 + 2 * p];
            float b[8];
            *(float4*)&b[0] = *(const float4*)&Ks[kk][tx * 8 + 0];
            *(float4*)&b[4] = *(const float4*)&Ks[kk][tx * 8 + 4];
            u64t bb[8];
#pragma unroll
            for (int j = 0; j < 8; j++) bb[j] = dup2(b[j]);
#pragma unroll
            for (int p = 0; p < 4; p++)
#pragma unroll
                for (int j = 0; j < 8; j++) ffma2(acc2[p][j], a2[p], bb[j]);
        }
        __syncthreads();
    }

    const float scale = 0.125f;
    bool diag = (kt == qt);
#pragma unroll
    for (int p = 0; p < 4; p++) {
        float r0[8], r1[8];
#pragma unroll
        for (int j = 0; j < 8; j++) unpack2(acc2[p][j], r0[j], r1[j]);
#pragma unroll
        for (int half = 0; half < 2; half++) {
            int q = qt * 128 + ty * 8 + 2 * p + half;
            int kbase = kt * 128 + tx * 8;
            const float* rr = half ? r1 : r0;
            float vv[8];
#pragma unroll
            for (int j = 0; j < 8; j++) {
                float s = rr[j] * scale;
                vv[j] = (diag && (kbase + j > q)) ? -INFINITY : s;
            }
            float* dst = &g_P[((size_t)bh * SEQ + q) * SEQ + kbase];
            *(float4*)&dst[0] = *(float4*)&vv[0];
            *(float4*)&dst[4] = *(float4*)&vv[4];
        }
    }
}

// ---------------- K3: exact top-64 threshold + masked softmax ----------------
// v2: fused hist+max on load; compact selected top-8-bit bin; 3 cheap passes
// over compacted candidates only.
__global__ __launch_bounds__(256) void topk_softmax_kernel()
{
    int row = blockIdx.x;
    int bh = row >> 11;
    int q = row & (SEQ - 1);
    size_t base = ((size_t)bh * SEQ + q) * SEQ;
    int L = q + 1;
    int tid = threadIdx.x;
    int lane = tid & 31;
    int warp = tid >> 5;

    __shared__ float sc[SEQ];
    __shared__ unsigned cand[SEQ];
    __shared__ unsigned hist[8][256];
    __shared__ unsigned sufS[256];
    __shared__ unsigned cntS[256];
    __shared__ unsigned warpTot[8];
    __shared__ unsigned ballots[8];
    __shared__ unsigned s_prefix;
    __shared__ int s_kk;
    __shared__ int s_cnt;
    __shared__ float red[8];
    __shared__ float s_bval;

    bool doSel = (L > TOPK);

    // zero hist (for pass 1), init counters
    for (int i = tid; i < 8 * 256; i += 256) ((unsigned*)hist)[i] = 0;
    if (tid == 0) { s_kk = TOPK; s_cnt = 0; }
    __syncthreads();

    // fused: load row + per-warp top-8-bit histogram + running max
    float m = -INFINITY;
    for (int i = tid; i < L; i += 256) {
        float v = g_P[base + i];
        sc[i] = v;
        m = fmaxf(m, v);
        if (doSel) {
            unsigned u = __float_as_uint(v);
            unsigned key = (u & 0x80000000u) ? ~u : (u | 0x80000000u);
            atomicAdd(&hist[warp][key >> 24], 1u);
        }
    }
#pragma unroll
    for (int off = 16; off; off >>= 1) m = fmaxf(m, __shfl_xor_sync(0xFFFFFFFFu, m, off));
    if (lane == 0) red[warp] = m;
    __syncthreads();
    {
        float mm = red[0];
#pragma unroll
        for (int w = 1; w < 8; w++) mm = fmaxf(mm, red[w]);
        m = mm;
    }

    float thresh = -INFINITY;
    if (doSel) {
        // ---- pass 1 select on top-8 bits (bins already built) ----
        unsigned cnt = 0;
#pragma unroll
        for (int w = 0; w < 8; w++) cnt += hist[w][tid];
        unsigned s = cnt;
#pragma unroll
        for (int off = 1; off < 32; off <<= 1) {
            unsigned t = __shfl_down_sync(0xFFFFFFFFu, s, off);
            if (lane + off < 32) s += t;
        }
        if (lane == 0) warpTot[warp] = s;
        __syncthreads();
        unsigned hi = 0;
        for (int w2 = warp + 1; w2 < 8; w2++) hi += warpTot[w2];
        unsigned S = s + hi;
        sufS[tid] = S;
        cntS[tid] = cnt;
        unsigned bal = __ballot_sync(0xFFFFFFFFu, S >= (unsigned)TOPK);
        if (lane == 0) ballots[warp] = bal;
        __syncthreads();
        if (tid == 0) {
            int sel = 0;
            for (int w = 7; w >= 0; w--) {
                if (ballots[w]) { sel = w * 32 + (31 - __clz(ballots[w])); break; }
            }
            s_kk = TOPK - (int)(sufS[sel] - cntS[sel]);
            s_prefix = (unsigned)sel << 24;
        }
        __syncthreads();
        unsigned prefix = s_prefix;
        unsigned selTop = prefix >> 24;

        // ---- compact candidates (keys sharing the selected top byte) ----
        for (int i = tid; i < L; i += 256) {
            unsigned u = __float_as_uint(sc[i]);
            unsigned key = (u & 0x80000000u) ? ~u : (u | 0x80000000u);
            if ((key >> 24) == selTop) {
                int idx = atomicAdd(&s_cnt, 1);
                cand[idx] = key;
            }
        }
        __syncthreads();
        int C = s_cnt;
        unsigned himask = 0xFF000000u;
        int kk = s_kk;

        // ---- 3 radix passes over candidates only ----
        for (int p = 16; p >= 0; p -= 8) {
            for (int i = tid; i < 8 * 256; i += 256) ((unsigned*)hist)[i] = 0;
            __syncthreads();
            for (int i = tid; i < C; i += 256) {
                unsigned key = cand[i];
                if ((key & himask) == prefix)
                    atomicAdd(&hist[warp][(key >> p) & 0xFFu], 1u);
            }
            __syncthreads();
            unsigned c2 = 0;
#pragma unroll
            for (int w = 0; w < 8; w++) c2 += hist[w][tid];
            unsigned s2 = c2;
#pragma unroll
            for (int off = 1; off < 32; off <<= 1) {
                unsigned t = __shfl_down_sync(0xFFFFFFFFu, s2, off);
                if (lane + off < 32) s2 += t;
            }
            if (lane == 0) warpTot[warp] = s2;
            __syncthreads();
            unsigned hi2 = 0;
            for (int w2 = warp + 1; w2 < 8; w2++) hi2 += warpTot[w2];
            unsigned S2 = s2 + hi2;
            sufS[tid] = S2;
            cntS[tid] = c2;
            unsigned bal2 = __ballot_sync(0xFFFFFFFFu, S2 >= (unsigned)kk);
            if (lane == 0) ballots[warp] = bal2;
            __syncthreads();
            if (tid == 0) {
                int sel = 0;
                for (int w = 7; w >= 0; w--) {
                    if (ballots[w]) { sel = w * 32 + (31 - __clz(ballots[w])); break; }
                }
                s_kk = s_kk - (int)(sufS[sel] - cntS[sel]);
                s_prefix = prefix | ((unsigned)sel << p);
            }
            __syncthreads();
            prefix = s_prefix;
            kk = s_kk;
            himask |= (0xFFu << p);
            __syncthreads();
        }
        unsigned key = prefix;
        unsigned u = (key & 0x80000000u) ? (key & 0x7FFFFFFFu) : ~key;
        thresh = __uint_as_float(u);
    }

    // exp + sum over kept
    float sum = 0.0f;
    for (int i = tid; i < L; i += 256) {
        float v = sc[i];
        float e = (v >= thresh) ? __expf(v - m) : 0.0f;
        sc[i] = e;
        sum += e;
    }
#pragma unroll
    for (int off = 16; off; off >>= 1) sum += __shfl_xor_sync(0xFFFFFFFFu, sum, off);
    if (lane == 0) red[warp] = sum;
    __syncthreads();
    if (tid == 0) {
        float ss = 0.0f;
#pragma unroll
        for (int w = 0; w < 8; w++) ss += red[w];
        s_bval = ss;
    }
    __syncthreads();
    float inv = 1.0f / s_bval;

    for (int i = tid; i < L; i += 256) g_P[base + i] = sc[i] * inv;
    int tileEnd = ((q >> 7) + 1) << 7;
    for (int i = L + tid; i < tileEnd; i += 256) g_P[base + i] = 0.0f;
}

// ---------------- K4: O = P @ V  split-bf16 tensor cores ---------------------
__global__ __launch_bounds__(256) void av_bf16_kernel()
{
    int qt = blockIdx.x;
    int bh = blockIdx.y;

    __shared__ __nv_bfloat16 Phi[128][40], Plo[128][40];
    __shared__ __nv_bfloat16 Vhi[32][72], Vlo[32][72];

    int tid = threadIdx.x;
    int lane = tid & 31;
    int wid = tid >> 5;
    int wm = wid & 3;
    int wn = wid >> 2;

    float acc[2][4][4];
#pragma unroll
    for (int mi = 0; mi < 2; mi++)
#pragma unroll
        for (int ni = 0; ni < 4; ni++)
#pragma unroll
            for (int r = 0; r < 4; r++) acc[mi][ni][r] = 0.0f;

    int nk = (qt + 1) * 128;
    int pr = tid >> 1, pc = (tid & 1) * 16;
    int vr = tid >> 3, vc = (tid & 7) * 8;
    const float* Pbase = &g_P[((size_t)bh * SEQ + qt * 128 + pr) * SEQ + pc];

    for (int kb = 0; kb < nk; kb += 32) {
#pragma unroll
        for (int t = 0; t < 4; t++) {
            float4 p = *(const float4*)&Pbase[kb + t * 4];
            __nv_bfloat16 h0, l0, h1, l1;
            split_bf16(p.x, h0, l0); split_bf16(p.y, h1, l1);
            *(__nv_bfloat162*)&Phi[pr][pc + t * 4] = __nv_bfloat162(h0, h1);
            *(__nv_bfloat162*)&Plo[pr][pc + t * 4] = __nv_bfloat162(l0, l1);
            split_bf16(p.z, h0, l0); split_bf16(p.w, h1, l1);
            *(__nv_bfloat162*)&Phi[pr][pc + t * 4 + 2] = __nv_bfloat162(h0, h1);
            *(__nv_bfloat162*)&Plo[pr][pc + t * 4 + 2] = __nv_bfloat162(l0, l1);
        }
        const float* Vg = &g_V[((size_t)bh * SEQ + kb + vr) * HDIM + vc];
#pragma unroll
        for (int t = 0; t < 2; t++) {
            float4 v = *(const float4*)&Vg[t * 4];
            __nv_bfloat16 h0, l0, h1, l1;
            split_bf16(v.x, h0, l0); split_bf16(v.y, h1, l1);
            *(__nv_bfloat162*)&Vhi[vr][vc + t * 4] = __nv_bfloat162(h0, h1);
            *(__nv_bfloat162*)&Vlo[vr][vc + t * 4] = __nv_bfloat162(l0, l1);
            split_bf16(v.z, h0, l0); split_bf16(v.w, h1, l1);
            *(__nv_bfloat162*)&Vhi[vr][vc + t * 4 + 2] = __nv_bfloat162(h0, h1);
            *(__nv_bfloat162*)&Vlo[vr][vc + t * 4 + 2] = __nv_bfloat162(l0, l1);
        }
        __syncthreads();
#pragma unroll
        for (int ks = 0; ks < 2; ks++) {
            int kk = ks * 16;
            uint32_t bhr[4][2], blr[4][2];
#pragma unroll
            for (int ni = 0; ni < 4; ni++) {
                ldmB2t(smem_u32(&Vhi[kk + (lane & 15)][wn * 32 + ni * 8]), bhr[ni][0], bhr[ni][1]);
                ldmB2t(smem_u32(&Vlo[kk + (lane & 15)][wn * 32 + ni * 8]), blr[ni][0], blr[ni][1]);
            }
#pragma unroll
            for (int mi = 0; mi < 2; mi++) {
                int arow = wm * 32 + mi * 16 + (lane & 15);
                int acol = kk + ((lane >> 4) << 3);
                uint32_t ah0, ah1, ah2, ah3, al0, al1, al2, al3;
                ldmA4(smem_u32(&Phi[arow][acol]), ah0, ah1, ah2, ah3);
                ldmA4(smem_u32(&Plo[arow][acol]), al0, al1, al2, al3);
#pragma unroll
                for (int ni = 0; ni < 4; ni++) {
                    mma16816(acc[mi][ni], ah0, ah1, ah2, ah3, bhr[ni][0], bhr[ni][1]);
                    mma16816(acc[mi][ni], al0, al1, al2, al3, bhr[ni][0], bhr[ni][1]);
                    mma16816(acc[mi][ni], ah0, ah1, ah2, ah3, blr[ni][0], blr[ni][1]);
                }
            }
        }
        __syncthreads();
    }

    int b = bh / NHEADS;
    int h = bh - b * NHEADS;
#pragma unroll
    for (int mi = 0; mi < 2; mi++) {
#pragma unroll
        for (int ni = 0; ni < 4; ni++) {
            int q0 = qt * 128 + wm * 32 + mi * 16 + (lane >> 2);
            int d0 = wn * 32 + ni * 8 + (lane & 3) * 2;
#pragma unroll
            for (int half = 0; half < 2; half++) {
                int q = q0 + half * 8;
                float2* dst = (float2*)&g_O[(size_t)(b * SEQ + q) * DMODEL + h * HDIM + d0];
                *dst = make_float2(acc[mi][ni][half * 2 + 0], acc[mi][ni][half * 2 + 1]);
            }
        }
    }
}

// ---------------- launch ------------------------------------------------------
extern "C" void kernel_launch(void* const* d_in, const int* in_sizes, int n_in,
                              void* d_out, int out_size)
{
    const float* h_ssm = (const float*)d_in[0];
    const float* gate  = (const float*)d_in[1];
    const float* Wq = (const float*)d_in[2];
    const float* bq = (const float*)d_in[3];
    const float* Wk = (const float*)d_in[4];
    const float* bk = (const float*)d_in[5];
    const float* Wv = (const float*)d_in[6];
    const float* bv = (const float*)d_in[7];
    const float* Wo = (const float*)d_in[8];
    const float* bo = (const float*)d_in[9];
    float* out = (float*)d_out;

    dim3 gProj(DMODEL / 128, NROWS / 128);          // (8, 32)
    gemm_kernel<<<gProj, 256>>>(h_ssm, Wq, bq, 0);
    gemm_kernel<<<gProj, 256>>>(h_ssm, Wk, bk, 1);
    gemm_bf16_kernel<<<gProj, 256>>>(h_ssm, Wv, bv, nullptr, nullptr, 2);

    scores_kernel<<<dim3(SEQ / 128, SEQ / 128, BH), 256>>>();
    topk_softmax_kernel<<<dim3(BH * SEQ), 256>>>();
    av_bf16_kernel<<<dim3(SEQ / 128, BH), 256>>>();

    gemm_bf16_kernel<<<gProj, 256>>>(nullptr, Wo, bo, out, gate, 3);
}

// round 8
// speedup vs baseline: 1.7988x; 1.0560x over previous
#include <cuda_runtime.h>
#include <cuda_bf16.h>
#include <math.h>
#include <stdint.h>

// Problem constants
#define BATCH 2
#define SEQ 2048
#define DMODEL 1024
#define NHEADS 16
#define HDIM 64
#define TOPK 64
#define NROWS (BATCH * SEQ)          // 4096
#define BH (BATCH * NHEADS)          // 32
#define CAP 80                       // kept-slot capacity (64 + tie headroom)

// ---------------- scratch (device globals; allocation-free rule) -------------
__device__ float g_Q[(size_t)BH * SEQ * HDIM];   // [bh, s, d] 16MB
__device__ float g_K[(size_t)BH * SEQ * HDIM];   // 16MB
__device__ float g_V[(size_t)BH * SEQ * HDIM];   // 16MB
__device__ float g_P[(size_t)BH * SEQ * SEQ];    // raw scores, 512MB
__device__ int   g_PI[(size_t)BH * SEQ * CAP];   // kept key indices
__device__ float g_PV[(size_t)BH * SEQ * CAP];   // kept normalized probs
__device__ int   g_CNT[(size_t)BH * SEQ];        // kept count per row
__device__ float g_O[(size_t)NROWS * DMODEL];    // attn output pre-Wo, 16MB

// ---------------- f32x2 packed-fma helpers (Blackwell dual-rate fp32) --------
typedef unsigned long long u64t;
__device__ __forceinline__ u64t dup2(float x) {
    u64t d;
    unsigned u = __float_as_uint(x);
    asm("mov.b64 %0, {%1, %1};" : "=l"(d) : "r"(u));
    return d;
}
__device__ __forceinline__ void ffma2(u64t& c, u64t a, u64t b) {
    asm("fma.rn.f32x2 %0, %1, %2, %0;" : "+l"(c) : "l"(a), "l"(b));
}
__device__ __forceinline__ void unpack2(u64t d, float& x, float& y) {
    unsigned lo, hi;
    asm("mov.b64 {%0, %1}, %2;" : "=r"(lo), "=r"(hi) : "l"(d));
    x = __uint_as_float(lo);
    y = __uint_as_float(hi);
}

// ---------------- tensor-core helpers ----------------------------------------
__device__ __forceinline__ uint32_t smem_u32(const void* p) {
    return (uint32_t)__cvta_generic_to_shared(p);
}
__device__ __forceinline__ void ldmA4(uint32_t addr, uint32_t& r0, uint32_t& r1,
                                      uint32_t& r2, uint32_t& r3) {
    asm volatile("ldmatrix.sync.aligned.m8n8.x4.shared.b16 {%0,%1,%2,%3}, [%4];"
                 : "=r"(r0), "=r"(r1), "=r"(r2), "=r"(r3) : "r"(addr));
}
__device__ __forceinline__ void ldmB2t(uint32_t addr, uint32_t& r0, uint32_t& r1) {
    asm volatile("ldmatrix.sync.aligned.m8n8.x2.trans.shared.b16 {%0,%1}, [%2];"
                 : "=r"(r0), "=r"(r1) : "r"(addr));
}
__device__ __forceinline__ void mma16816(float* c, uint32_t a0, uint32_t a1,
                                         uint32_t a2, uint32_t a3,
                                         uint32_t b0, uint32_t b1) {
    asm volatile(
        "mma.sync.aligned.m16n8k16.row.col.f32.bf16.bf16.f32 "
        "{%0,%1,%2,%3}, {%4,%5,%6,%7}, {%8,%9}, {%0,%1,%2,%3};"
        : "+f"(c[0]), "+f"(c[1]), "+f"(c[2]), "+f"(c[3])
        : "r"(a0), "r"(a1), "r"(a2), "r"(a3), "r"(b0), "r"(b1));
}
__device__ __forceinline__ void split_bf16(float x, __nv_bfloat16& hi, __nv_bfloat16& lo) {
    hi = __float2bfloat16(x);
    lo = __float2bfloat16(x - __bfloat162float(hi));
}

// ---------------- K1: 128x128x16 SGEMM w/ f32x2 (Q/K projections) ------------
__global__ __launch_bounds__(256) void gemm_kernel(
    const float* __restrict__ A,
    const float* __restrict__ W,
    const float* __restrict__ bias,
    int mode)   // 0 -> g_Q, 1 -> g_K
{
    __shared__ float As[16][132];
    __shared__ float Bs[16][128];

    const int K = DMODEL;
    const int NC = DMODEL;
    int tid = threadIdx.x;
    int tx = tid & 15;
    int ty = tid >> 4;
    int rowTile = blockIdx.y * 128;
    int colTile = blockIdx.x * 128;

    float* Op = (mode == 0) ? g_Q : g_K;

    int ar = tid >> 1;
    int ac8 = (tid & 1) * 8;
    int br = tid >> 4;
    int bc8 = (tid & 15) * 8;

    u64t acc2[4][8];
#pragma unroll
    for (int p = 0; p < 4; p++)
#pragma unroll
        for (int j = 0; j < 8; j++) acc2[p][j] = 0ull;

    const float* aptr = &A[(size_t)(rowTile + ar) * K];
    const float* bptr = &W[(size_t)colTile + bc8];

    {
        float4 a0 = *(const float4*)&aptr[ac8 + 0];
        float4 a1 = *(const float4*)&aptr[ac8 + 4];
        As[ac8 + 0][ar] = a0.x; As[ac8 + 1][ar] = a0.y;
        As[ac8 + 2][ar] = a0.z; As[ac8 + 3][ar] = a0.w;
        As[ac8 + 4][ar] = a1.x; As[ac8 + 5][ar] = a1.y;
        As[ac8 + 6][ar] = a1.z; As[ac8 + 7][ar] = a1.w;
        *(float4*)&Bs[br][bc8 + 0] = *(const float4*)&bptr[(size_t)br * NC + 0];
        *(float4*)&Bs[br][bc8 + 4] = *(const float4*)&bptr[(size_t)br * NC + 4];
    }
    __syncthreads();

    for (int k0 = 0; k0 < K; k0 += 16) {
        bool has = (k0 + 16) < K;
        float4 pa0, pa1, pb0, pb1;
        if (has) {
            pa0 = *(const float4*)&aptr[k0 + 16 + ac8 + 0];
            pa1 = *(const float4*)&aptr[k0 + 16 + ac8 + 4];
            pb0 = *(const float4*)&bptr[(size_t)(k0 + 16 + br) * NC + 0];
            pb1 = *(const float4*)&bptr[(size_t)(k0 + 16 + br) * NC + 4];
        }
#pragma unroll
        for (int kk = 0; kk < 16; kk++) {
            u64t a2[4];
#pragma unroll
            for (int p = 0; p < 4; p++)
                a2[p] = *(const u64t*)&As[kk][ty * 8 + 2 * p];
            float b[8];
            *(float4*)&b[0] = *(const float4*)&Bs[kk][tx * 8 + 0];
            *(float4*)&b[4] = *(const float4*)&Bs[kk][tx * 8 + 4];
            u64t bb[8];
#pragma unroll
            for (int j = 0; j < 8; j++) bb[j] = dup2(b[j]);
#pragma unroll
            for (int p = 0; p < 4; p++)
#pragma unroll
                for (int j = 0; j < 8; j++) ffma2(acc2[p][j], a2[p], bb[j]);
        }
        __syncthreads();
        if (has) {
            As[ac8 + 0][ar] = pa0.x; As[ac8 + 1][ar] = pa0.y;
            As[ac8 + 2][ar] = pa0.z; As[ac8 + 3][ar] = pa0.w;
            As[ac8 + 4][ar] = pa1.x; As[ac8 + 5][ar] = pa1.y;
            As[ac8 + 6][ar] = pa1.z; As[ac8 + 7][ar] = pa1.w;
            *(float4*)&Bs[br][bc8 + 0] = pb0;
            *(float4*)&Bs[br][bc8 + 4] = pb1;
            __syncthreads();
        }
    }

#pragma unroll
    for (int p = 0; p < 4; p++) {
        float r0[8], r1[8];
#pragma unroll
        for (int j = 0; j < 8; j++) unpack2(acc2[p][j], r0[j], r1[j]);
#pragma unroll
        for (int half = 0; half < 2; half++) {
            int m = rowTile + ty * 8 + 2 * p + half;
            int b = m / SEQ;
            int s = m - b * SEQ;
            const float* rr = half ? r1 : r0;
#pragma unroll
            for (int j = 0; j < 8; j++) {
                int n = colTile + tx * 8 + j;
                int h = n >> 6;
                int d = n & 63;
                Op[((size_t)(b * NHEADS + h) * SEQ + s) * HDIM + d] = rr[j] + bias[n];
            }
        }
    }
}

// ---------------- K1b: 128x128 split-bf16 tensor-core GEMM -------------------
// mode 2: g_V = h_ssm @ Wv + bv   ([b,h,s,d] layout)
// mode 3: out = (g_O @ Wo + bo) * gate
__global__ __launch_bounds__(256) void gemm_bf16_kernel(
    const float* __restrict__ A,
    const float* __restrict__ W,
    const float* __restrict__ bias,
    float* __restrict__ outp,
    const float* __restrict__ gate,
    int mode)
{
    __shared__ __nv_bfloat16 Ahi[128][40], Alo[128][40];
    __shared__ __nv_bfloat16 Bhi[32][136], Blo[32][136];

    const int K = DMODEL;
    const int NC = DMODEL;
    int tid = threadIdx.x;
    int lane = tid & 31;
    int wid = tid >> 5;
    int wm = wid & 1;
    int wn = wid >> 1;
    int rowTile = blockIdx.y * 128;
    int colTile = blockIdx.x * 128;

    const float* Ap = (mode == 3) ? g_O : A;

    int ar = tid >> 1, ac = (tid & 1) * 16;
    int br = tid >> 3, bc = (tid & 7) * 16;
    const float* aptr = &Ap[(size_t)(rowTile + ar) * K + ac];
    const float* bptr = &W[(size_t)br * NC + colTile + bc];

    float acc[4][4][4];
#pragma unroll
    for (int mi = 0; mi < 4; mi++)
#pragma unroll
        for (int ni = 0; ni < 4; ni++)
#pragma unroll
            for (int r = 0; r < 4; r++) acc[mi][ni][r] = 0.0f;

    float4 pa[4], pb[4];
#pragma unroll
    for (int t = 0; t < 4; t++) {
        pa[t] = *(const float4*)&aptr[t * 4];
        pb[t] = *(const float4*)&bptr[t * 4];
    }
#pragma unroll
    for (int t = 0; t < 4; t++) {
        float v[4] = {pa[t].x, pa[t].y, pa[t].z, pa[t].w};
        __nv_bfloat16 h0, l0, h1, l1;
        split_bf16(v[0], h0, l0); split_bf16(v[1], h1, l1);
        *(__nv_bfloat162*)&Ahi[ar][ac + t * 4] = __nv_bfloat162(h0, h1);
        *(__nv_bfloat162*)&Alo[ar][ac + t * 4] = __nv_bfloat162(l0, l1);
        split_bf16(v[2], h0, l0); split_bf16(v[3], h1, l1);
        *(__nv_bfloat162*)&Ahi[ar][ac + t * 4 + 2] = __nv_bfloat162(h0, h1);
        *(__nv_bfloat162*)&Alo[ar][ac + t * 4 + 2] = __nv_bfloat162(l0, l1);
        float w[4] = {pb[t].x, pb[t].y, pb[t].z, pb[t].w};
        split_bf16(w[0], h0, l0); split_bf16(w[1], h1, l1);
        *(__nv_bfloat162*)&Bhi[br][bc + t * 4] = __nv_bfloat162(h0, h1);
        *(__nv_bfloat162*)&Blo[br][bc + t * 4] = __nv_bfloat162(l0, l1);
        split_bf16(w[2], h0, l0); split_bf16(w[3], h1, l1);
        *(__nv_bfloat162*)&Bhi[br][bc + t * 4 + 2] = __nv_bfloat162(h0, h1);
        *(__nv_bfloat162*)&Blo[br][bc + t * 4 + 2] = __nv_bfloat162(l0, l1);
    }
    __syncthreads();

    for (int s = 0; s < K / 32; s++) {
        bool has = (s + 1) < K / 32;
        if (has) {
            int k0 = (s + 1) * 32;
#pragma unroll
            for (int t = 0; t < 4; t++) {
                pa[t] = *(const float4*)&aptr[k0 + t * 4];
                pb[t] = *(const float4*)&bptr[(size_t)k0 * NC + t * 4];
            }
        }
#pragma unroll
        for (int ks = 0; ks < 2; ks++) {
            int kk = ks * 16;
            uint32_t bhr[4][2], blr[4][2];
#pragma unroll
            for (int ni = 0; ni < 4; ni++) {
                ldmB2t(smem_u32(&Bhi[kk + (lane & 15)][wn * 32 + ni * 8]), bhr[ni][0], bhr[ni][1]);
                ldmB2t(smem_u32(&Blo[kk + (lane & 15)][wn * 32 + ni * 8]), blr[ni][0], blr[ni][1]);
            }
#pragma unroll
            for (int mi = 0; mi < 4; mi++) {
                int arow = wm * 64 + mi * 16 + (lane & 15);
                int acol = kk + ((lane >> 4) << 3);
                uint32_t ah0, ah1, ah2, ah3, al0, al1, al2, al3;
                ldmA4(smem_u32(&Ahi[arow][acol]), ah0, ah1, ah2, ah3);
                ldmA4(smem_u32(&Alo[arow][acol]), al0, al1, al2, al3);
#pragma unroll
                for (int ni = 0; ni < 4; ni++) {
                    mma16816(acc[mi][ni], ah0, ah1, ah2, ah3, bhr[ni][0], bhr[ni][1]);
                    mma16816(acc[mi][ni], al0, al1, al2, al3, bhr[ni][0], bhr[ni][1]);
                    mma16816(acc[mi][ni], ah0, ah1, ah2, ah3, blr[ni][0], blr[ni][1]);
                }
            }
        }
        __syncthreads();
        if (has) {
#pragma unroll
            for (int t = 0; t < 4; t++) {
                float v[4] = {pa[t].x, pa[t].y, pa[t].z, pa[t].w};
                __nv_bfloat16 h0, l0, h1, l1;
                split_bf16(v[0], h0, l0); split_bf16(v[1], h1, l1);
                *(__nv_bfloat162*)&Ahi[ar][ac + t * 4] = __nv_bfloat162(h0, h1);
                *(__nv_bfloat162*)&Alo[ar][ac + t * 4] = __nv_bfloat162(l0, l1);
                split_bf16(v[2], h0, l0); split_bf16(v[3], h1, l1);
                *(__nv_bfloat162*)&Ahi[ar][ac + t * 4 + 2] = __nv_bfloat162(h0, h1);
                *(__nv_bfloat162*)&Alo[ar][ac + t * 4 + 2] = __nv_bfloat162(l0, l1);
                float w[4] = {pb[t].x, pb[t].y, pb[t].z, pb[t].w};
                split_bf16(w[0], h0, l0); split_bf16(w[1], h1, l1);
                *(__nv_bfloat162*)&Bhi[br][bc + t * 4] = __nv_bfloat162(h0, h1);
                *(__nv_bfloat162*)&Blo[br][bc + t * 4] = __nv_bfloat162(l0, l1);
                split_bf16(w[2], h0, l0); split_bf16(w[3], h1, l1);
                *(__nv_bfloat162*)&Bhi[br][bc + t * 4 + 2] = __nv_bfloat162(h0, h1);
                *(__nv_bfloat162*)&Blo[br][bc + t * 4 + 2] = __nv_bfloat162(l0, l1);
            }
            __syncthreads();
        }
    }

#pragma unroll
    for (int mi = 0; mi < 4; mi++) {
#pragma unroll
        for (int ni = 0; ni < 4; ni++) {
            int row0 = rowTile + wm * 64 + mi * 16 + (lane >> 2);
            int col0 = colTile + wn * 32 + ni * 8 + (lane & 3) * 2;
            float b0 = bias[col0], b1 = bias[col0 + 1];
#pragma unroll
            for (int half = 0; half < 2; half++) {
                int m = row0 + half * 8;
                float v0 = acc[mi][ni][half * 2 + 0] + b0;
                float v1 = acc[mi][ni][half * 2 + 1] + b1;
                if (mode == 2) {
                    int b = m / SEQ;
                    int ss = m - b * SEQ;
                    int h = col0 >> 6;
                    int d = col0 & 63;
                    float2* dst = (float2*)&g_V[((size_t)(b * NHEADS + h) * SEQ + ss) * HDIM + d];
                    *dst = make_float2(v0, v1);
                } else {
                    float gm = gate[m];
                    float2* dst = (float2*)&outp[(size_t)m * DMODEL + col0];
                    *dst = make_float2(v0 * gm, v1 * gm);
                }
            }
        }
    }
}

// ---------------- K2: scores = Q K^T / 8, causal, 128x128, f32x2 -------------
__global__ __launch_bounds__(256) void scores_kernel()
{
    int kt = blockIdx.x;
    int qt = blockIdx.y;
    int bh = blockIdx.z;
    if (kt > qt) return;

    __shared__ float Qs[32][132];
    __shared__ float Ks[32][132];

    int tid = threadIdx.x;
    int tx = tid & 15;
    int ty = tid >> 4;
    const float* Qg = &g_Q[((size_t)bh * SEQ + qt * 128) * HDIM];
    const float* Kg = &g_K[((size_t)bh * SEQ + kt * 128) * HDIM];

    u64t acc2[4][8];
#pragma unroll
    for (int p = 0; p < 4; p++)
#pragma unroll
        for (int j = 0; j < 8; j++) acc2[p][j] = 0ull;

    int lr = tid >> 1;
    int lc = (tid & 1) * 16;

    for (int d0 = 0; d0 < HDIM; d0 += 32) {
#pragma unroll
        for (int t = 0; t < 4; t++) {
            float4 qv = *(const float4*)&Qg[(size_t)lr * HDIM + d0 + lc + t * 4];
            Qs[lc + t * 4 + 0][lr] = qv.x; Qs[lc + t * 4 + 1][lr] = qv.y;
            Qs[lc + t * 4 + 2][lr] = qv.z; Qs[lc + t * 4 + 3][lr] = qv.w;
            float4 kv = *(const float4*)&Kg[(size_t)lr * HDIM + d0 + lc + t * 4];
            Ks[lc + t * 4 + 0][lr] = kv.x; Ks[lc + t * 4 + 1][lr] = kv.y;
            Ks[lc + t * 4 + 2][lr] = kv.z; Ks[lc + t * 4 + 3][lr] = kv.w;
        }
        __syncthreads();
#pragma unroll
        for (int kk = 0; kk < 32; kk++) {
            u64t a2[4];
#pragma unroll
            for (int p = 0; p < 4; p++)
                a2[p] = *(const u64t*)&Qs[kk][ty * 8 + 2 * p];
            float b[8];
            *(float4*)&b[0] = *(const float4*)&Ks[kk][tx * 8 + 0];
            *(float4*)&b[4] = *(const float4*)&Ks[kk][tx * 8 + 4];
            u64t bb[8];
#pragma unroll
            for (int j = 0; j < 8; j++) bb[j] = dup2(b[j]);
#pragma unroll
            for (int p = 0; p < 4; p++)
#pragma unroll
                for (int j = 0; j < 8; j++) ffma2(acc2[p][j], a2[p], bb[j]);
        }
        __syncthreads();
    }

    const float scale = 0.125f;
    bool diag = (kt == qt);
#pragma unroll
    for (int p = 0; p < 4; p++) {
        float r0[8], r1[8];
#pragma unroll
        for (int j = 0; j < 8; j++) unpack2(acc2[p][j], r0[j], r1[j]);
#pragma unroll
        for (int half = 0; half < 2; half++) {
            int q = qt * 128 + ty * 8 + 2 * p + half;
            int kbase = kt * 128 + tx * 8;
            const float* rr = half ? r1 : r0;
            float vv[8];
#pragma unroll
            for (int j = 0; j < 8; j++) {
                float s = rr[j] * scale;
                vv[j] = (diag && (kbase + j > q)) ? -INFINITY : s;
            }
            float* dst = &g_P[((size_t)bh * SEQ + q) * SEQ + kbase];
            *(float4*)&dst[0] = *(float4*)&vv[0];
            *(float4*)&dst[4] = *(float4*)&vv[4];
        }
    }
}

// ---------------- K3: exact top-64 threshold + softmax -> SPARSE output ------
// Reads raw score row, finds exact 64th-largest threshold (radix), compacts
// kept entries as (idx, normalized prob) pairs. No dense prob write-back.
__global__ __launch_bounds__(256) void topk_softmax_kernel()
{
    int row = blockIdx.x;
    int bh = row >> 11;
    int q = row & (SEQ - 1);
    size_t base = ((size_t)bh * SEQ + q) * SEQ;
    int L = q + 1;
    int tid = threadIdx.x;
    int lane = tid & 31;
    int warp = tid >> 5;

    __shared__ float sc[SEQ];
    __shared__ unsigned cand[SEQ];
    __shared__ unsigned hist[8][256];
    __shared__ unsigned sufS[256];
    __shared__ unsigned cntS[256];
    __shared__ unsigned warpTot[8];
    __shared__ unsigned ballots[8];
    __shared__ unsigned s_prefix;
    __shared__ int s_kk;
    __shared__ int s_cnt;
    __shared__ int s_keep;
    __shared__ float red[8];
    __shared__ float s_sum;
    __shared__ int s_pi[CAP];
    __shared__ float s_pv[CAP];

    bool doSel = (L > TOPK);

    for (int i = tid; i < 8 * 256; i += 256) ((unsigned*)hist)[i] = 0;
    if (tid == 0) { s_kk = TOPK; s_cnt = 0; s_keep = 0; }
    __syncthreads();

    // fused: load row + per-warp top-8-bit histogram + running max
    float m = -INFINITY;
    for (int i = tid; i < L; i += 256) {
        float v = g_P[base + i];
        sc[i] = v;
        m = fmaxf(m, v);
        if (doSel) {
            unsigned u = __float_as_uint(v);
            unsigned key = (u & 0x80000000u) ? ~u : (u | 0x80000000u);
            atomicAdd(&hist[warp][key >> 24], 1u);
        }
    }
#pragma unroll
    for (int off = 16; off; off >>= 1) m = fmaxf(m, __shfl_xor_sync(0xFFFFFFFFu, m, off));
    if (lane == 0) red[warp] = m;
    __syncthreads();
    {
        float mm = red[0];
#pragma unroll
        for (int w = 1; w < 8; w++) mm = fmaxf(mm, red[w]);
        m = mm;
    }

    float thresh = -INFINITY;
    if (doSel) {
        // ---- pass 1 select on top-8 bits ----
        unsigned cnt = 0;
#pragma unroll
        for (int w = 0; w < 8; w++) cnt += hist[w][tid];
        unsigned s = cnt;
#pragma unroll
        for (int off = 1; off < 32; off <<= 1) {
            unsigned t = __shfl_down_sync(0xFFFFFFFFu, s, off);
            if (lane + off < 32) s += t;
        }
        if (lane == 0) warpTot[warp] = s;
        __syncthreads();
        unsigned hi = 0;
        for (int w2 = warp + 1; w2 < 8; w2++) hi += warpTot[w2];
        unsigned S = s + hi;
        sufS[tid] = S;
        cntS[tid] = cnt;
        unsigned bal = __ballot_sync(0xFFFFFFFFu, S >= (unsigned)TOPK);
        if (lane == 0) ballots[warp] = bal;
        __syncthreads();
        if (tid == 0) {
            int sel = 0;
            for (int w = 7; w >= 0; w--) {
                if (ballots[w]) { sel = w * 32 + (31 - __clz(ballots[w])); break; }
            }
            s_kk = TOPK - (int)(sufS[sel] - cntS[sel]);
            s_prefix = (unsigned)sel << 24;
        }
        __syncthreads();
        unsigned prefix = s_prefix;
        unsigned selTop = prefix >> 24;

        // ---- compact candidates ----
        for (int i = tid; i < L; i += 256) {
            unsigned u = __float_as_uint(sc[i]);
            unsigned key = (u & 0x80000000u) ? ~u : (u | 0x80000000u);
            if ((key >> 24) == selTop) {
                int idx = atomicAdd(&s_cnt, 1);
                cand[idx] = key;
            }
        }
        __syncthreads();
        int C = s_cnt;
        unsigned himask = 0xFF000000u;
        int kk = s_kk;

        // ---- 3 radix passes over candidates only ----
        for (int p = 16; p >= 0; p -= 8) {
            for (int i = tid; i < 8 * 256; i += 256) ((unsigned*)hist)[i] = 0;
            __syncthreads();
            for (int i = tid; i < C; i += 256) {
                unsigned key = cand[i];
                if ((key & himask) == prefix)
                    atomicAdd(&hist[warp][(key >> p) & 0xFFu], 1u);
            }
            __syncthreads();
            unsigned c2 = 0;
#pragma unroll
            for (int w = 0; w < 8; w++) c2 += hist[w][tid];
            unsigned s2 = c2;
#pragma unroll
            for (int off = 1; off < 32; off <<= 1) {
                unsigned t = __shfl_down_sync(0xFFFFFFFFu, s2, off);
                if (lane + off < 32) s2 += t;
            }
            if (lane == 0) warpTot[warp] = s2;
            __syncthreads();
            unsigned hi2 = 0;
            for (int w2 = warp + 1; w2 < 8; w2++) hi2 += warpTot[w2];
            unsigned S2 = s2 + hi2;
            sufS[tid] = S2;
            cntS[tid] = c2;
            unsigned bal2 = __ballot_sync(0xFFFFFFFFu, S2 >= (unsigned)kk);
            if (lane == 0) ballots[warp] = bal2;
            __syncthreads();
            if (tid == 0) {
                int sel = 0;
                for (int w = 7; w >= 0; w--) {
                    if (ballots[w]) { sel = w * 32 + (31 - __clz(ballots[w])); break; }
                }
                s_kk = s_kk - (int)(sufS[sel] - cntS[sel]);
                s_prefix = prefix | ((unsigned)sel << p);
            }
            __syncthreads();
            prefix = s_prefix;
            kk = s_kk;
            himask |= (0xFFu << p);
            __syncthreads();
        }
        unsigned key = prefix;
        unsigned u = (key & 0x80000000u) ? (key & 0x7FFFFFFFu) : ~key;
        thresh = __uint_as_float(u);
    }

    // ---- compact kept entries (v >= thresh) with unnormalized exp ----
    for (int i = tid; i < L; i += 256) {
        float v = sc[i];
        if (v >= thresh) {
            int pos = atomicAdd(&s_keep, 1);
            if (pos < CAP) {
                s_pi[pos] = i;
                s_pv[pos] = __expf(v - m);
            }
        }
    }
    __syncthreads();
    int cnt = min(s_keep, CAP);

    // sum over kept (warp 0)
    if (warp == 0) {
        float ss = 0.0f;
        for (int j = lane; j < cnt; j += 32) ss += s_pv[j];
#pragma unroll
        for (int off = 16; off; off >>= 1) ss += __shfl_xor_sync(0xFFFFFFFFu, ss, off);
        if (lane == 0) s_sum = ss;
    }
    __syncthreads();
    float inv = 1.0f / s_sum;

    if (tid < cnt) {
        g_PI[(size_t)row * CAP + tid] = s_pi[tid];
        g_PV[(size_t)row * CAP + tid] = s_pv[tid] * inv;
    }
    if (tid == 0) g_CNT[row] = cnt;
}

// ---------------- K4: sparse O = P @ V (one warp per query row, fp32) --------
__global__ __launch_bounds__(256) void av_sparse_kernel()
{
    int row = blockIdx.x * 8 + (threadIdx.x >> 5);   // 0 .. BH*SEQ-1
    int lane = threadIdx.x & 31;
    int bh = row >> 11;
    int s = row & (SEQ - 1);
    int b = bh >> 4;
    int h = bh & 15;

    int cnt = g_CNT[row];
    const float* Vb = &g_V[(size_t)bh * SEQ * HDIM];
    const int* PI = &g_PI[(size_t)row * CAP];
    const float* PV = &g_PV[(size_t)row * CAP];

    float a0 = 0.0f, a1 = 0.0f;
    for (int c = 0; c < cnt; c += 32) {
        int myIdx = 0;
        float myP = 0.0f;
        if (c + lane < cnt) {
            myIdx = PI[c + lane];
            myP = PV[c + lane];
        }
        int nn = min(32, cnt - c);
#pragma unroll 8
        for (int jj = 0; jj < nn; jj++) {
            int idx = __shfl_sync(0xFFFFFFFFu, myIdx, jj);
            float p = __shfl_sync(0xFFFFFFFFu, myP, jj);
            float2 v = *(const float2*)&Vb[(size_t)idx * HDIM + lane * 2];
            a0 = fmaf(p, v.x, a0);
            a1 = fmaf(p, v.y, a1);
        }
    }

    float2* dst = (float2*)&g_O[(size_t)(b * SEQ + s) * DMODEL + h * HDIM + lane * 2];
    *dst = make_float2(a0, a1);
}

// ---------------- launch ------------------------------------------------------
extern "C" void kernel_launch(void* const* d_in, const int* in_sizes, int n_in,
                              void* d_out, int out_size)
{
    const float* h_ssm = (const float*)d_in[0];
    const float* gate  = (const float*)d_in[1];
    const float* Wq = (const float*)d_in[2];
    const float* bq = (const float*)d_in[3];
    const float* Wk = (const float*)d_in[4];
    const float* bk = (const float*)d_in[5];
    const float* Wv = (const float*)d_in[6];
    const float* bv = (const float*)d_in[7];
    const float* Wo = (const float*)d_in[8];
    const float* bo = (const float*)d_in[9];
    float* out = (float*)d_out;

    dim3 gProj(DMODEL / 128, NROWS / 128);          // (8, 32)
    gemm_kernel<<<gProj, 256>>>(h_ssm, Wq, bq, 0);
    gemm_kernel<<<gProj, 256>>>(h_ssm, Wk, bk, 1);
    gemm_bf16_kernel<<<gProj, 256>>>(h_ssm, Wv, bv, nullptr, nullptr, 2);

    scores_kernel<<<dim3(SEQ / 128, SEQ / 128, BH), 256>>>();
    topk_softmax_kernel<<<dim3(BH * SEQ), 256>>>();
    av_sparse_kernel<<<dim3(BH * SEQ / 8), 256>>>();

    gemm_bf16_kernel<<<gProj, 256>>>(nullptr, Wo, bo, out, gate, 3);
}